// round 4
// baseline (speedup 1.0000x reference)
#include <cuda_runtime.h>
#include <cuda_bf16.h>

#define N_NODES 50000
#define N_EDGES 800000
#define HID 128
#define EDGE_DIM 4
#define LAYERS 4
#define NUM_GRAPHS 512

// Scratch (device globals: no allocation allowed)
__device__ float g_x[N_NODES * HID];
__device__ float g_agg[N_NODES * HID];
__device__ float g_gsum[NUM_GRAPHS * HID];
__device__ float g_gcnt[NUM_GRAPHS];

__device__ __forceinline__ float silu_f(float v) { return v / (1.0f + __expf(-v)); }

// ---------------------------------------------------------------------------
// Kernel 1: embedding lookup + zero scratch
// ---------------------------------------------------------------------------
__global__ void embed_kernel(const int* __restrict__ z, const float* __restrict__ emb) {
    int idx = blockIdx.x * 256 + threadIdx.x;
    if (idx < N_NODES * HID) {
        int n = idx >> 7, j = idx & 127;
        g_x[idx] = emb[z[n] * HID + j];
        g_agg[idx] = 0.0f;
    }
    if (idx < NUM_GRAPHS * HID) g_gsum[idx] = 0.0f;
    if (idx < NUM_GRAPHS) g_gcnt[idx] = 0.0f;
}

// ---------------------------------------------------------------------------
// Kernel 2: fused edge MLP + scatter-add.
// Block = 64 edges, 256 threads. Thread (tx=tid%32, ty=tid/32) computes
// 8 rows (ty*8..+7) x 4 cols (tx*4..+3) of the [64 x 128] output tile.
// Dynamic smem: Ws[64*128] (W chunk) + Ab[64*128] (A-chunk stride 68 / h stride 128)
// ---------------------------------------------------------------------------
#define TE 64
#define AS_STRIDE 68  // 17 float4s: avoids STS bank conflicts on gather

__global__ void edge_kernel(const int* __restrict__ ei, const float* __restrict__ ea,
                            const float* __restrict__ ew1, const float* __restrict__ eb1,
                            const float* __restrict__ ew2, const float* __restrict__ eb2,
                            int layer) {
    extern __shared__ float sm[];
    float* Ws = sm;              // 8192 floats
    float* Ab = sm + 64 * 128;   // 8192 floats
    __shared__ int s_dst[TE];
    __shared__ int s_src[TE];

    const int tid = threadIdx.x;
    const int tx = tid & 31, ty = tid >> 5;
    const int e0 = blockIdx.x * TE;
    const float* W1 = ew1 + layer * (2 * HID + EDGE_DIM) * HID;
    const float* W2 = ew2 + layer * HID * HID;
    const int* srcI = ei;
    const int* dstI = ei + N_EDGES;

    if (tid < TE) { s_src[tid] = srcI[e0 + tid]; s_dst[tid] = dstI[e0 + tid]; }

    float acc[8][4];
#pragma unroll
    for (int r = 0; r < 8; r++)
#pragma unroll
        for (int c = 0; c < 4; c++) acc[r][c] = 0.0f;

    // ---- GEMM1 main: 4 chunks of K=64 over x[src] (ch 0,1) and x[dst] (ch 2,3)
    for (int ch = 0; ch < 4; ch++) {
        __syncthreads();
        // load W1 chunk [64 x 128]
        const float4* Wg = (const float4*)(W1 + ch * 64 * HID);
        float4* Ws4 = (float4*)Ws;
#pragma unroll
        for (int t = 0; t < 8; t++) Ws4[tid + t * 256] = Wg[tid + t * 256];
        // gather A chunk: 4 threads per edge row, each 4 float4
        {
            int row = tid >> 2;
            int q = tid & 3;
            int node = (ch < 2) ? s_src[row] : s_dst[row];
            const float4* Xg = (const float4*)(g_x + node * HID + (ch & 1) * 64);
            float4* A4 = (float4*)Ab;
#pragma unroll
            for (int t = 0; t < 4; t++) A4[row * 17 + q + t * 4] = Xg[q + t * 4];
        }
        __syncthreads();
#pragma unroll
        for (int k = 0; k < 64; k++) {
            float4 b = ((const float4*)Ws)[k * 32 + tx];
#pragma unroll
            for (int r = 0; r < 8; r++) {
                float a = Ab[(ty * 8 + r) * AS_STRIDE + k];
                acc[r][0] += a * b.x; acc[r][1] += a * b.y;
                acc[r][2] += a * b.z; acc[r][3] += a * b.w;
            }
        }
    }

    // ---- GEMM1 tail: edge_attr (K rows 256..259)
    __syncthreads();
    if (tid < 128) ((float4*)Ws)[tid] = ((const float4*)(W1 + 256 * HID))[tid];
    if (tid < TE) ((float4*)Ab)[tid * 17] = ((const float4*)ea)[e0 + tid];
    __syncthreads();
#pragma unroll
    for (int k = 0; k < 4; k++) {
        float4 b = ((const float4*)Ws)[k * 32 + tx];
#pragma unroll
        for (int r = 0; r < 8; r++) {
            float a = Ab[(ty * 8 + r) * AS_STRIDE + k];
            acc[r][0] += a * b.x; acc[r][1] += a * b.y;
            acc[r][2] += a * b.z; acc[r][3] += a * b.w;
        }
    }

    // ---- bias + silu -> h staged in Ab (stride 128), reset acc
    __syncthreads();
    {
        float4 b1 = ((const float4*)(eb1 + layer * HID))[tx];
#pragma unroll
        for (int r = 0; r < 8; r++) {
            int row = ty * 8 + r;
            float4 h;
            h.x = silu_f(acc[r][0] + b1.x);
            h.y = silu_f(acc[r][1] + b1.y);
            h.z = silu_f(acc[r][2] + b1.z);
            h.w = silu_f(acc[r][3] + b1.w);
            ((float4*)Ab)[row * 32 + tx] = h;
            acc[r][0] = acc[r][1] = acc[r][2] = acc[r][3] = 0.0f;
        }
    }

    // ---- GEMM2: h[64x128] @ W2[128x128], 2 chunks of K=64
    for (int ch = 0; ch < 2; ch++) {
        __syncthreads();
        const float4* Wg = (const float4*)(W2 + ch * 64 * HID);
        float4* Ws4 = (float4*)Ws;
#pragma unroll
        for (int t = 0; t < 8; t++) Ws4[tid + t * 256] = Wg[tid + t * 256];
        __syncthreads();
#pragma unroll
        for (int k = 0; k < 64; k++) {
            float4 b = ((const float4*)Ws)[k * 32 + tx];
#pragma unroll
            for (int r = 0; r < 8; r++) {
                float a = Ab[(ty * 8 + r) * 128 + ch * 64 + k];
                acc[r][0] += a * b.x; acc[r][1] += a * b.y;
                acc[r][2] += a * b.z; acc[r][3] += a * b.w;
            }
        }
    }

    // ---- bias + silu + float4 atomic scatter to agg[dst]
    {
        float4 b2 = ((const float4*)(eb2 + layer * HID))[tx];
#pragma unroll
        for (int r = 0; r < 8; r++) {
            int row = ty * 8 + r;
            float4 m;
            m.x = silu_f(acc[r][0] + b2.x);
            m.y = silu_f(acc[r][1] + b2.y);
            m.z = silu_f(acc[r][2] + b2.z);
            m.w = silu_f(acc[r][3] + b2.w);
            int d = s_dst[row];
            atomicAdd((float4*)(g_agg + d * HID + tx * 4), m);
        }
    }
}

// ---------------------------------------------------------------------------
// Kernel 3: node update x = silu(concat(x, agg) @ nw + nb); re-zero agg.
// Block = 64 nodes, 256 threads, same micro-tile as edge kernel.
// ---------------------------------------------------------------------------
__global__ void node_kernel(const float* __restrict__ nw, const float* __restrict__ nb,
                            int layer) {
    extern __shared__ float sm[];
    float* Ws = sm;               // 8192 floats
    float* As = sm + 64 * 128;    // 64 * 68 floats
    const int tid = threadIdx.x;
    const int tx = tid & 31, ty = tid >> 5;
    const int n0 = blockIdx.x * 64;
    const float* W = nw + layer * 2 * HID * HID;

    float acc[8][4];
#pragma unroll
    for (int r = 0; r < 8; r++)
#pragma unroll
        for (int c = 0; c < 4; c++) acc[r][c] = 0.0f;

    for (int ch = 0; ch < 4; ch++) {
        __syncthreads();
        const float4* Wg = (const float4*)(W + ch * 64 * HID);
        float4* Ws4 = (float4*)Ws;
#pragma unroll
        for (int t = 0; t < 8; t++) Ws4[tid + t * 256] = Wg[tid + t * 256];
        {
            int row = tid >> 2;
            int q = tid & 3;
            int n = n0 + row;
            const float* base = ((ch < 2) ? g_x : g_agg);
            const float4* Xg = (const float4*)(base + n * HID + (ch & 1) * 64);
            float4* A4 = (float4*)As;
#pragma unroll
            for (int t = 0; t < 4; t++) {
                float4 v = make_float4(0.f, 0.f, 0.f, 0.f);
                if (n < N_NODES) v = Xg[q + t * 4];
                A4[row * 17 + q + t * 4] = v;
            }
        }
        __syncthreads();
#pragma unroll
        for (int k = 0; k < 64; k++) {
            float4 b = ((const float4*)Ws)[k * 32 + tx];
#pragma unroll
            for (int r = 0; r < 8; r++) {
                float a = As[(ty * 8 + r) * AS_STRIDE + k];
                acc[r][0] += a * b.x; acc[r][1] += a * b.y;
                acc[r][2] += a * b.z; acc[r][3] += a * b.w;
            }
        }
    }

    {
        float4 bb = ((const float4*)(nb + layer * HID))[tx];
        float4 z4 = make_float4(0.f, 0.f, 0.f, 0.f);
#pragma unroll
        for (int r = 0; r < 8; r++) {
            int n = n0 + ty * 8 + r;
            if (n < N_NODES) {
                float4 h;
                h.x = silu_f(acc[r][0] + bb.x);
                h.y = silu_f(acc[r][1] + bb.y);
                h.z = silu_f(acc[r][2] + bb.z);
                h.w = silu_f(acc[r][3] + bb.w);
                ((float4*)(g_x + n * HID))[tx] = h;
                ((float4*)(g_agg + n * HID))[tx] = z4;  // zero for next layer
            }
        }
    }
}

// ---------------------------------------------------------------------------
// Kernel 4: pooling (segment sum + counts via atomics)
// ---------------------------------------------------------------------------
__global__ void pool_kernel(const int* __restrict__ batch) {
    int idx = blockIdx.x * 256 + threadIdx.x;
    if (idx < N_NODES * 32) {
        int n = idx >> 5, c = idx & 31;
        int b = batch[n];
        float4 v = ((const float4*)g_x)[idx];
        atomicAdd((float4*)(g_gsum + b * HID + c * 4), v);
        if (c == 0) atomicAdd(&g_gcnt[b], 1.0f);
    }
}

// ---------------------------------------------------------------------------
// Kernel 5: readout MLP per graph
// ---------------------------------------------------------------------------
__global__ void readout_kernel(const float* __restrict__ rw1, const float* __restrict__ rb1,
                               const float* __restrict__ rw2, const float* __restrict__ rb2,
                               float* __restrict__ out) {
    __shared__ float gsh[HID];
    __shared__ float part[4];
    int g = blockIdx.x, j = threadIdx.x;
    float cnt = fmaxf(g_gcnt[g], 1.0f);
    gsh[j] = g_gsum[g * HID + j] / cnt;
    __syncthreads();
    float s = rb1[j];
#pragma unroll
    for (int k = 0; k < HID; k++) s += gsh[k] * rw1[k * HID + j];
    float v = silu_f(s) * rw2[j];
#pragma unroll
    for (int off = 16; off > 0; off >>= 1) v += __shfl_xor_sync(0xffffffffu, v, off);
    if ((j & 31) == 0) part[j >> 5] = v;
    __syncthreads();
    if (j == 0) out[g] = part[0] + part[1] + part[2] + part[3] + rb2[0];
}

// ---------------------------------------------------------------------------
extern "C" void kernel_launch(void* const* d_in, const int* in_sizes, int n_in,
                              void* d_out, int out_size) {
    const int*   z    = (const int*)d_in[0];
    const int*   ei   = (const int*)d_in[1];
    const float* ea   = (const float*)d_in[2];
    const int*   batch= (const int*)d_in[3];
    const float* emb  = (const float*)d_in[4];
    const float* ew1  = (const float*)d_in[5];
    const float* eb1  = (const float*)d_in[6];
    const float* ew2  = (const float*)d_in[7];
    const float* eb2  = (const float*)d_in[8];
    const float* nw   = (const float*)d_in[9];
    const float* nb   = (const float*)d_in[10];
    const float* rw1  = (const float*)d_in[11];
    const float* rb1  = (const float*)d_in[12];
    const float* rw2  = (const float*)d_in[13];
    const float* rb2  = (const float*)d_in[14];
    float* out = (float*)d_out;

    const int EDGE_SMEM = 2 * 64 * 128 * (int)sizeof(float);           // 65536
    const int NODE_SMEM = (64 * 128 + 64 * AS_STRIDE) * (int)sizeof(float); // 50176
    cudaFuncSetAttribute(edge_kernel, cudaFuncAttributeMaxDynamicSharedMemorySize, EDGE_SMEM);
    cudaFuncSetAttribute(node_kernel, cudaFuncAttributeMaxDynamicSharedMemorySize, NODE_SMEM);

    embed_kernel<<<(N_NODES * HID + 255) / 256, 256>>>(z, emb);
    for (int l = 0; l < LAYERS; l++) {
        edge_kernel<<<N_EDGES / TE, 256, EDGE_SMEM>>>(ei, ea, ew1, eb1, ew2, eb2, l);
        node_kernel<<<(N_NODES + 63) / 64, 256, NODE_SMEM>>>(nw, nb, l);
    }
    pool_kernel<<<(N_NODES * 32 + 255) / 256, 256>>>(batch);
    readout_kernel<<<NUM_GRAPHS, HID>>>(rw1, rb1, rw2, rb2, out);
}

// round 5
// speedup vs baseline: 1.1597x; 1.1597x over previous
#include <cuda_runtime.h>
#include <cuda_bf16.h>
#include <cstdint>

#define N_NODES 50000
#define N_EDGES 800000
#define HID 128
#define EDGE_DIM 4
#define LAYERS 4
#define NUM_GRAPHS 512

// Scratch (device globals: no allocation allowed)
__device__ float g_x[N_NODES * HID];
__device__ float g_agg[N_NODES * HID];
__device__ float g_gsum[NUM_GRAPHS * HID];
__device__ float g_gcnt[NUM_GRAPHS];

// Split tf32 weights (hi + lo), W1 padded 260 -> 264 rows (zeros)
#define K1P 264
__device__ float g_w1hi[LAYERS * K1P * HID];
__device__ float g_w1lo[LAYERS * K1P * HID];
__device__ float g_w2hi[LAYERS * HID * HID];
__device__ float g_w2lo[LAYERS * HID * HID];

__device__ __forceinline__ float silu_f(float v) { return v / (1.0f + __expf(-v)); }

__device__ __forceinline__ uint32_t f2tf(float f) {
    uint32_t u;
    asm("cvt.rna.tf32.f32 %0, %1;" : "=r"(u) : "f"(f));
    return u;
}

__device__ __forceinline__ void mma8(float* d, const uint32_t* a, uint32_t b0, uint32_t b1) {
    asm volatile(
        "mma.sync.aligned.m16n8k8.row.col.f32.tf32.tf32.f32 "
        "{%0,%1,%2,%3}, {%4,%5,%6,%7}, {%8,%9}, {%0,%1,%2,%3};"
        : "+f"(d[0]), "+f"(d[1]), "+f"(d[2]), "+f"(d[3])
        : "r"(a[0]), "r"(a[1]), "r"(a[2]), "r"(a[3]), "r"(b0), "r"(b1));
}

// ---------------------------------------------------------------------------
// Weight split: hi = rna_tf32(w), lo = rna_tf32(w - hi)
// ---------------------------------------------------------------------------
__global__ void split_w_kernel(const float* __restrict__ ew1, const float* __restrict__ ew2) {
    int idx = blockIdx.x * 256 + threadIdx.x;
    const int n1 = LAYERS * K1P * HID;
    if (idx < n1) {
        int l = idx / (K1P * HID);
        int r = idx - l * (K1P * HID);
        int k = r >> 7, n = r & 127;
        float w = (k < 2 * HID + EDGE_DIM) ? ew1[l * (2 * HID + EDGE_DIM) * HID + k * HID + n] : 0.0f;
        float hi = __uint_as_float(f2tf(w));
        float lo = __uint_as_float(f2tf(w - hi));
        g_w1hi[idx] = hi;
        g_w1lo[idx] = lo;
    }
    if (idx < LAYERS * HID * HID) {
        float w = ew2[idx];
        float hi = __uint_as_float(f2tf(w));
        float lo = __uint_as_float(f2tf(w - hi));
        g_w2hi[idx] = hi;
        g_w2lo[idx] = lo;
    }
}

// ---------------------------------------------------------------------------
// Kernel 1: embedding lookup + zero scratch
// ---------------------------------------------------------------------------
__global__ void embed_kernel(const int* __restrict__ z, const float* __restrict__ emb) {
    int idx = blockIdx.x * 256 + threadIdx.x;
    if (idx < N_NODES * HID) {
        int n = idx >> 7, j = idx & 127;
        g_x[idx] = emb[z[n] * HID + j];
        g_agg[idx] = 0.0f;
    }
    if (idx < NUM_GRAPHS * HID) g_gsum[idx] = 0.0f;
    if (idx < NUM_GRAPHS) g_gcnt[idx] = 0.0f;
}

// ---------------------------------------------------------------------------
// Edge MLP on tensor cores: tf32 mma.sync, split weights.
// Block = 128 edges, 256 threads (8 warps). Warp (wm = wid&3, wn = wid>>2)
// computes rows [wm*32, +32) x cols [wn*64, +64) via m16n8k8 fragments.
// smem: Wh[32][136] | Wl[32][136] | Hs[128][132]  (As[128][36] aliases Hs)
// ---------------------------------------------------------------------------
#define EM 128
#define WST 136  // W smem row stride (floats): (8t+g)%32 distinct -> conflict-free
#define HST 132  // H smem row stride
#define AST 36   // A smem row stride

#define EDGE_SMEM ((2 * 32 * WST + 128 * HST) * (int)sizeof(float))

__global__ __launch_bounds__(256, 2)
void edge_tc_kernel(const int* __restrict__ ei, const float* __restrict__ ea,
                    const float* __restrict__ eb1, const float* __restrict__ eb2,
                    int layer) {
    extern __shared__ float sm[];
    float* Wh = sm;
    float* Wl = sm + 32 * WST;
    float* Hs = sm + 2 * 32 * WST;
    float* As = Hs;  // alias: A chunks use first 128*36 floats of Hs region
    __shared__ int s_src[EM], s_dst[EM];

    const int tid = threadIdx.x;
    const int lane = tid & 31, wid = tid >> 5;
    const int g = lane >> 2, t = lane & 3;
    const int wm = wid & 3, wn = wid >> 2;
    const int e0 = blockIdx.x * EM;

    const float* W1h = g_w1hi + layer * K1P * HID;
    const float* W1l = g_w1lo + layer * K1P * HID;
    const float* W2h = g_w2hi + layer * HID * HID;
    const float* W2l = g_w2lo + layer * HID * HID;

    if (tid < EM) {
        s_src[tid] = ei[e0 + tid];
        s_dst[tid] = ei[N_EDGES + e0 + tid];
    }

    float c[2][8][4];
#pragma unroll
    for (int mi = 0; mi < 2; mi++)
#pragma unroll
        for (int ni = 0; ni < 8; ni++)
#pragma unroll
            for (int q = 0; q < 4; q++) c[mi][ni][q] = 0.0f;

    // ================= GEMM 1: K = 256 (x[src] || x[dst]) in 8 chunks of 32
    for (int ch = 0; ch < 8; ch++) {
        __syncthreads();
        // stage split-W chunk [32][128]
        {
            const float4* Wg1 = (const float4*)(W1h + ch * 32 * HID);
            const float4* Wg2 = (const float4*)(W1l + ch * 32 * HID);
#pragma unroll
            for (int i = 0; i < 4; i++) {
                int f = tid * 4 + i;
                int k = f >> 5, n4 = f & 31;
                ((float4*)(Wh + k * WST))[n4] = Wg1[f];
                ((float4*)(Wl + k * WST))[n4] = Wg2[f];
            }
        }
        // gather + tf32-quantize A chunk [128][32]
        {
            int row = tid >> 1, q = tid & 1;
            int node = (ch < 4) ? s_src[row] : s_dst[row];
            const float4* Xg = (const float4*)(g_x + node * HID + (ch & 3) * 32);
#pragma unroll
            for (int i = 0; i < 4; i++) {
                float4 v = Xg[q * 4 + i];
                float4 tv;
                tv.x = __uint_as_float(f2tf(v.x));
                tv.y = __uint_as_float(f2tf(v.y));
                tv.z = __uint_as_float(f2tf(v.z));
                tv.w = __uint_as_float(f2tf(v.w));
                ((float4*)(As + row * AST))[q * 4 + i] = tv;
            }
        }
        __syncthreads();
#pragma unroll
        for (int k8 = 0; k8 < 4; k8++) {
            const int kb = k8 * 8;
            uint32_t a[2][4];
#pragma unroll
            for (int mi = 0; mi < 2; mi++) {
                int r0 = wm * 32 + mi * 16 + g;
                a[mi][0] = __float_as_uint(As[r0 * AST + kb + t]);
                a[mi][1] = __float_as_uint(As[(r0 + 8) * AST + kb + t]);
                a[mi][2] = __float_as_uint(As[r0 * AST + kb + t + 4]);
                a[mi][3] = __float_as_uint(As[(r0 + 8) * AST + kb + t + 4]);
            }
#pragma unroll
            for (int ni = 0; ni < 8; ni++) {
                int n = wn * 64 + ni * 8 + g;
                uint32_t bh0 = __float_as_uint(Wh[(kb + t) * WST + n]);
                uint32_t bh1 = __float_as_uint(Wh[(kb + t + 4) * WST + n]);
                uint32_t bl0 = __float_as_uint(Wl[(kb + t) * WST + n]);
                uint32_t bl1 = __float_as_uint(Wl[(kb + t + 4) * WST + n]);
                mma8(c[0][ni], a[0], bh0, bh1);
                mma8(c[1][ni], a[1], bh0, bh1);
                mma8(c[0][ni], a[0], bl0, bl1);
                mma8(c[1][ni], a[1], bl0, bl1);
            }
        }
    }

    // ---- GEMM1 tail: edge_attr rows (W1 rows 256..263, cols 4..7 zero-padded)
    __syncthreads();
    {
        int k = tid >> 5, n4 = tid & 31;  // 256 float4 per matrix
        ((float4*)(Wh + k * WST))[n4] = ((const float4*)(W1h + 256 * HID))[tid];
        ((float4*)(Wl + k * WST))[n4] = ((const float4*)(W1l + 256 * HID))[tid];
        if (tid < EM) {
            float4 v = ((const float4*)ea)[e0 + tid];
            float4 tv;
            tv.x = __uint_as_float(f2tf(v.x));
            tv.y = __uint_as_float(f2tf(v.y));
            tv.z = __uint_as_float(f2tf(v.z));
            tv.w = __uint_as_float(f2tf(v.w));
            ((float4*)(As + tid * AST))[0] = tv;
            ((float4*)(As + tid * AST))[1] = make_float4(0.f, 0.f, 0.f, 0.f);
        }
    }
    __syncthreads();
    {
        uint32_t a[2][4];
#pragma unroll
        for (int mi = 0; mi < 2; mi++) {
            int r0 = wm * 32 + mi * 16 + g;
            a[mi][0] = __float_as_uint(As[r0 * AST + t]);
            a[mi][1] = __float_as_uint(As[(r0 + 8) * AST + t]);
            a[mi][2] = __float_as_uint(As[r0 * AST + t + 4]);
            a[mi][3] = __float_as_uint(As[(r0 + 8) * AST + t + 4]);
        }
#pragma unroll
        for (int ni = 0; ni < 8; ni++) {
            int n = wn * 64 + ni * 8 + g;
            uint32_t bh0 = __float_as_uint(Wh[t * WST + n]);
            uint32_t bh1 = __float_as_uint(Wh[(t + 4) * WST + n]);
            uint32_t bl0 = __float_as_uint(Wl[t * WST + n]);
            uint32_t bl1 = __float_as_uint(Wl[(t + 4) * WST + n]);
            mma8(c[0][ni], a[0], bh0, bh1);
            mma8(c[1][ni], a[1], bh0, bh1);
            mma8(c[0][ni], a[0], bl0, bl1);
            mma8(c[1][ni], a[1], bl0, bl1);
        }
    }

    // ---- epilogue 1: bias + silu, stage tf32 h into Hs[128][132]
    __syncthreads();
    {
        const float* B1 = eb1 + layer * HID;
#pragma unroll
        for (int ni = 0; ni < 8; ni++) {
            int n = wn * 64 + ni * 8 + t * 2;
            float b0 = B1[n], b1v = B1[n + 1];
#pragma unroll
            for (int mi = 0; mi < 2; mi++) {
                int r0 = wm * 32 + mi * 16 + g;
                float2 h0, h1;
                h0.x = __uint_as_float(f2tf(silu_f(c[mi][ni][0] + b0)));
                h0.y = __uint_as_float(f2tf(silu_f(c[mi][ni][1] + b1v)));
                h1.x = __uint_as_float(f2tf(silu_f(c[mi][ni][2] + b0)));
                h1.y = __uint_as_float(f2tf(silu_f(c[mi][ni][3] + b1v)));
                *(float2*)(Hs + r0 * HST + n) = h0;
                *(float2*)(Hs + (r0 + 8) * HST + n) = h1;
                c[mi][ni][0] = c[mi][ni][1] = c[mi][ni][2] = c[mi][ni][3] = 0.0f;
            }
        }
    }
    __syncthreads();

    // ================= GEMM 2: h[128x128] @ W2, 4 chunks of 32
    for (int ch = 0; ch < 4; ch++) {
        {
            const float4* Wg1 = (const float4*)(W2h + ch * 32 * HID);
            const float4* Wg2 = (const float4*)(W2l + ch * 32 * HID);
#pragma unroll
            for (int i = 0; i < 4; i++) {
                int f = tid * 4 + i;
                int k = f >> 5, n4 = f & 31;
                ((float4*)(Wh + k * WST))[n4] = Wg1[f];
                ((float4*)(Wl + k * WST))[n4] = Wg2[f];
            }
        }
        __syncthreads();
#pragma unroll
        for (int k8 = 0; k8 < 4; k8++) {
            const int kb = ch * 32 + k8 * 8;
            uint32_t a[2][4];
#pragma unroll
            for (int mi = 0; mi < 2; mi++) {
                int r0 = wm * 32 + mi * 16 + g;
                a[mi][0] = __float_as_uint(Hs[r0 * HST + kb + t]);
                a[mi][1] = __float_as_uint(Hs[(r0 + 8) * HST + kb + t]);
                a[mi][2] = __float_as_uint(Hs[r0 * HST + kb + t + 4]);
                a[mi][3] = __float_as_uint(Hs[(r0 + 8) * HST + kb + t + 4]);
            }
#pragma unroll
            for (int ni = 0; ni < 8; ni++) {
                int n = wn * 64 + ni * 8 + g;
                uint32_t bh0 = __float_as_uint(Wh[(kb - ch * 32 + t) * WST + n]);
                uint32_t bh1 = __float_as_uint(Wh[(kb - ch * 32 + t + 4) * WST + n]);
                uint32_t bl0 = __float_as_uint(Wl[(kb - ch * 32 + t) * WST + n]);
                uint32_t bl1 = __float_as_uint(Wl[(kb - ch * 32 + t + 4) * WST + n]);
                mma8(c[0][ni], a[0], bh0, bh1);
                mma8(c[1][ni], a[1], bh0, bh1);
                mma8(c[0][ni], a[0], bl0, bl1);
                mma8(c[1][ni], a[1], bl0, bl1);
            }
        }
        __syncthreads();
    }

    // ---- epilogue 2: bias + silu -> stage msg fp32 into Hs, then scatter
    {
        const float* B2 = eb2 + layer * HID;
#pragma unroll
        for (int ni = 0; ni < 8; ni++) {
            int n = wn * 64 + ni * 8 + t * 2;
            float b0 = B2[n], b1v = B2[n + 1];
#pragma unroll
            for (int mi = 0; mi < 2; mi++) {
                int r0 = wm * 32 + mi * 16 + g;
                float2 m0, m1;
                m0.x = silu_f(c[mi][ni][0] + b0);
                m0.y = silu_f(c[mi][ni][1] + b1v);
                m1.x = silu_f(c[mi][ni][2] + b0);
                m1.y = silu_f(c[mi][ni][3] + b1v);
                *(float2*)(Hs + r0 * HST + n) = m0;
                *(float2*)(Hs + (r0 + 8) * HST + n) = m1;
            }
        }
    }
    __syncthreads();
    // coalesced scatter: each warp handles one edge row at a time (32 float4 = 512B)
#pragma unroll
    for (int i = 0; i < 16; i++) {
        int idx = tid + i * 256;
        int row = idx >> 5, c4 = idx & 31;
        float4 v = ((const float4*)(Hs + row * HST))[c4];
        atomicAdd((float4*)(g_agg + s_dst[row] * HID + c4 * 4), v);
    }
}

// ---------------------------------------------------------------------------
// Kernel 3: node update x = silu(concat(x, agg) @ nw + nb); re-zero agg. (FFMA)
// ---------------------------------------------------------------------------
#define AS_STRIDE 68

__global__ void node_kernel(const float* __restrict__ nw, const float* __restrict__ nb,
                            int layer) {
    extern __shared__ float sm[];
    float* Ws = sm;
    float* As = sm + 64 * 128;
    const int tid = threadIdx.x;
    const int tx = tid & 31, ty = tid >> 5;
    const int n0 = blockIdx.x * 64;
    const float* W = nw + layer * 2 * HID * HID;

    float acc[8][4];
#pragma unroll
    for (int r = 0; r < 8; r++)
#pragma unroll
        for (int c = 0; c < 4; c++) acc[r][c] = 0.0f;

    for (int ch = 0; ch < 4; ch++) {
        __syncthreads();
        const float4* Wg = (const float4*)(W + ch * 64 * HID);
        float4* Ws4 = (float4*)Ws;
#pragma unroll
        for (int t = 0; t < 8; t++) Ws4[tid + t * 256] = Wg[tid + t * 256];
        {
            int row = tid >> 2;
            int q = tid & 3;
            int n = n0 + row;
            const float* base = ((ch < 2) ? g_x : g_agg);
            const float4* Xg = (const float4*)(base + n * HID + (ch & 1) * 64);
            float4* A4 = (float4*)As;
#pragma unroll
            for (int t = 0; t < 4; t++) {
                float4 v = make_float4(0.f, 0.f, 0.f, 0.f);
                if (n < N_NODES) v = Xg[q + t * 4];
                A4[row * 17 + q + t * 4] = v;
            }
        }
        __syncthreads();
#pragma unroll
        for (int k = 0; k < 64; k++) {
            float4 b = ((const float4*)Ws)[k * 32 + tx];
#pragma unroll
            for (int r = 0; r < 8; r++) {
                float a = As[(ty * 8 + r) * AS_STRIDE + k];
                acc[r][0] += a * b.x; acc[r][1] += a * b.y;
                acc[r][2] += a * b.z; acc[r][3] += a * b.w;
            }
        }
    }

    {
        float4 bb = ((const float4*)(nb + layer * HID))[tx];
        float4 z4 = make_float4(0.f, 0.f, 0.f, 0.f);
#pragma unroll
        for (int r = 0; r < 8; r++) {
            int n = n0 + ty * 8 + r;
            if (n < N_NODES) {
                float4 h;
                h.x = silu_f(acc[r][0] + bb.x);
                h.y = silu_f(acc[r][1] + bb.y);
                h.z = silu_f(acc[r][2] + bb.z);
                h.w = silu_f(acc[r][3] + bb.w);
                ((float4*)(g_x + n * HID))[tx] = h;
                ((float4*)(g_agg + n * HID))[tx] = z4;
            }
        }
    }
}

// ---------------------------------------------------------------------------
// Kernel 4: pooling
// ---------------------------------------------------------------------------
__global__ void pool_kernel(const int* __restrict__ batch) {
    int idx = blockIdx.x * 256 + threadIdx.x;
    if (idx < N_NODES * 32) {
        int n = idx >> 5, c = idx & 31;
        int b = batch[n];
        float4 v = ((const float4*)g_x)[idx];
        atomicAdd((float4*)(g_gsum + b * HID + c * 4), v);
        if (c == 0) atomicAdd(&g_gcnt[b], 1.0f);
    }
}

// ---------------------------------------------------------------------------
// Kernel 5: readout MLP per graph
// ---------------------------------------------------------------------------
__global__ void readout_kernel(const float* __restrict__ rw1, const float* __restrict__ rb1,
                               const float* __restrict__ rw2, const float* __restrict__ rb2,
                               float* __restrict__ out) {
    __shared__ float gsh[HID];
    __shared__ float part[4];
    int g = blockIdx.x, j = threadIdx.x;
    float cnt = fmaxf(g_gcnt[g], 1.0f);
    gsh[j] = g_gsum[g * HID + j] / cnt;
    __syncthreads();
    float s = rb1[j];
#pragma unroll
    for (int k = 0; k < HID; k++) s += gsh[k] * rw1[k * HID + j];
    float v = silu_f(s) * rw2[j];
#pragma unroll
    for (int off = 16; off > 0; off >>= 1) v += __shfl_xor_sync(0xffffffffu, v, off);
    if ((j & 31) == 0) part[j >> 5] = v;
    __syncthreads();
    if (j == 0) out[g] = part[0] + part[1] + part[2] + part[3] + rb2[0];
}

// ---------------------------------------------------------------------------
extern "C" void kernel_launch(void* const* d_in, const int* in_sizes, int n_in,
                              void* d_out, int out_size) {
    const int*   z    = (const int*)d_in[0];
    const int*   ei   = (const int*)d_in[1];
    const float* ea   = (const float*)d_in[2];
    const int*   batch= (const int*)d_in[3];
    const float* emb  = (const float*)d_in[4];
    const float* ew1  = (const float*)d_in[5];
    const float* eb1  = (const float*)d_in[6];
    const float* ew2  = (const float*)d_in[7];
    const float* eb2  = (const float*)d_in[8];
    const float* nw   = (const float*)d_in[9];
    const float* nb   = (const float*)d_in[10];
    const float* rw1  = (const float*)d_in[11];
    const float* rb1  = (const float*)d_in[12];
    const float* rw2  = (const float*)d_in[13];
    const float* rb2  = (const float*)d_in[14];
    float* out = (float*)d_out;

    const int NODE_SMEM = (64 * 128 + 64 * AS_STRIDE) * (int)sizeof(float);
    cudaFuncSetAttribute(edge_tc_kernel, cudaFuncAttributeMaxDynamicSharedMemorySize, EDGE_SMEM);
    cudaFuncSetAttribute(node_kernel, cudaFuncAttributeMaxDynamicSharedMemorySize, NODE_SMEM);

    split_w_kernel<<<(LAYERS * K1P * HID + 255) / 256, 256>>>(ew1, ew2);
    embed_kernel<<<(N_NODES * HID + 255) / 256, 256>>>(z, emb);
    for (int l = 0; l < LAYERS; l++) {
        edge_tc_kernel<<<N_EDGES / EM, 256, EDGE_SMEM>>>(ei, ea, eb1, eb2, l);
        node_kernel<<<(N_NODES + 63) / 64, 256, NODE_SMEM>>>(nw, nb, l);
    }
    pool_kernel<<<(N_NODES * 32 + 255) / 256, 256>>>(batch);
    readout_kernel<<<NUM_GRAPHS, HID>>>(rw1, rb1, rw2, rb2, out);
}

// round 7
// speedup vs baseline: 2.0911x; 1.8032x over previous
#include <cuda_runtime.h>
#include <cuda_bf16.h>
#include <cstdint>

#define N_NODES 50000
#define N_EDGES 800000
#define HID 128
#define EDGE_DIM 4
#define LAYERS 4
#define NUM_GRAPHS 512

// ------------------------- device scratch (no allocs allowed) ---------------
__device__ float g_x[N_NODES * HID];
__device__ float g_agg[N_NODES * HID];
__device__ float g_gsum[NUM_GRAPHS * HID];
__device__ float g_gcnt[NUM_GRAPHS];

// bf16 hi/lo split weights, TRANSPOSED per 32-k chunk: [l][kb][n=128][ki=32]
// W1: K padded 260 -> 288 (9 chunks). W2: 128 (4 chunks).
__device__ __nv_bfloat16 g_w1hi[LAYERS * 9 * 128 * 32];
__device__ __nv_bfloat16 g_w1lo[LAYERS * 9 * 128 * 32];
__device__ __nv_bfloat16 g_w2hi[LAYERS * 4 * 128 * 32];
__device__ __nv_bfloat16 g_w2lo[LAYERS * 4 * 128 * 32];

__device__ __forceinline__ float silu_f(float v) { return v / (1.0f + __expf(-v)); }

__device__ __forceinline__ uint32_t pbf(float a, float b) {
    __nv_bfloat162 t = __floats2bfloat162_rn(a, b);
    return *(uint32_t*)&t;
}

__device__ __forceinline__ void mma16(float* d, const uint32_t* a, uint32_t b0, uint32_t b1) {
    asm volatile(
        "mma.sync.aligned.m16n8k16.row.col.f32.bf16.bf16.f32 "
        "{%0,%1,%2,%3}, {%4,%5,%6,%7}, {%8,%9}, {%0,%1,%2,%3};"
        : "+f"(d[0]), "+f"(d[1]), "+f"(d[2]), "+f"(d[3])
        : "r"(a[0]), "r"(a[1]), "r"(a[2]), "r"(a[3]), "r"(b0), "r"(b1));
}

// ---------------------------------------------------------------------------
// Pack: hi = bf16(w), lo = bf16(w - hi), layout [l][kb][n][ki]
// ---------------------------------------------------------------------------
__global__ void pack_w_kernel(const float* __restrict__ ew1, const float* __restrict__ ew2) {
    int idx = blockIdx.x * 256 + threadIdx.x;
    if (idx < LAYERS * 9 * 128 * 32) {
        int l = idx / (9 * 128 * 32);
        int r = idx % (9 * 128 * 32);
        int kb = r / (128 * 32);
        int r2 = r % (128 * 32);
        int n = r2 >> 5, ki = r2 & 31;
        int kg = kb * 32 + ki;
        float w = (kg < 2 * HID + EDGE_DIM) ? ew1[(l * (2 * HID + EDGE_DIM) + kg) * HID + n] : 0.0f;
        __nv_bfloat16 hi = __float2bfloat16(w);
        __nv_bfloat16 lo = __float2bfloat16(w - __bfloat162float(hi));
        g_w1hi[idx] = hi;
        g_w1lo[idx] = lo;
    }
    if (idx < LAYERS * 4 * 128 * 32) {
        int l = idx / (4 * 128 * 32);
        int r = idx % (4 * 128 * 32);
        int kb = r / (128 * 32);
        int r2 = r % (128 * 32);
        int n = r2 >> 5, ki = r2 & 31;
        int kg = kb * 32 + ki;
        float w = ew2[(l * HID + kg) * HID + n];
        __nv_bfloat16 hi = __float2bfloat16(w);
        __nv_bfloat16 lo = __float2bfloat16(w - __bfloat162float(hi));
        g_w2hi[idx] = hi;
        g_w2lo[idx] = lo;
    }
}

// ---------------------------------------------------------------------------
// embedding lookup + zero scratch
// ---------------------------------------------------------------------------
__global__ void embed_kernel(const int* __restrict__ z, const float* __restrict__ emb) {
    int idx = blockIdx.x * 256 + threadIdx.x;
    if (idx < N_NODES * HID) {
        int n = idx >> 7, j = idx & 127;
        g_x[idx] = emb[z[n] * HID + j];
        g_agg[idx] = 0.0f;
    }
    if (idx < NUM_GRAPHS * HID) g_gsum[idx] = 0.0f;
    if (idx < NUM_GRAPHS) g_gcnt[idx] = 0.0f;
}

// ---------------------------------------------------------------------------
// Edge MLP: bf16 m16n8k16 mma.sync, hi/lo split weights.
// Block = 128 edges, 256 threads (8 warps). Warp (wm=wid&3, wn=wid>>2)
// owns rows [wm*32,+32) x cols [wn*64,+64).
// smem (bf16): Wh[128][40] | Wl[128][40] | Hs[128][136]  (A[128][40] aliases Hs;
// epilogue2 reuses Hs as float[128][68] per 64-col half)
// ---------------------------------------------------------------------------
#define KWP 40   // W / A bf16 row stride
#define HSB 136  // H bf16 row stride
#define EDGE_SMEM ((2 * 128 * KWP + 128 * HSB) * 2)

__global__ __launch_bounds__(256, 2)
void edge_tc_kernel(const int* __restrict__ ei, const float* __restrict__ ea,
                    const float* __restrict__ eb1, const float* __restrict__ eb2,
                    int layer) {
    extern __shared__ __nv_bfloat16 sm[];
    __nv_bfloat16* Wh = sm;                    // [128][40]
    __nv_bfloat16* Wl = Wh + 128 * KWP;        // [128][40]
    __nv_bfloat16* Hs = Wl + 128 * KWP;        // [128][136]
    __nv_bfloat16* As = Hs;                    // alias: A chunk [128][40]
    __shared__ int s_src[128], s_dst[128];
    __shared__ float s_b1[HID], s_b2[HID];

    const int tid = threadIdx.x;
    const int lane = tid & 31, wid = tid >> 5;
    const int g = lane >> 2, t = lane & 3;
    const int wm = wid & 3, wn = wid >> 2;
    const int e0 = blockIdx.x * 128;

    if (tid < 128) {
        s_src[tid] = ei[e0 + tid];
        s_dst[tid] = ei[N_EDGES + e0 + tid];
        s_b1[tid] = eb1[layer * HID + tid];
        s_b2[tid] = eb2[layer * HID + tid];
    }

    float c[2][8][4];
#pragma unroll
    for (int mi = 0; mi < 2; mi++)
#pragma unroll
        for (int ni = 0; ni < 8; ni++)
#pragma unroll
            for (int q = 0; q < 4; q++) c[mi][ni][q] = 0.0f;

    // ================= GEMM 1: 9 chunks of K=32 (8 data + 1 edge_attr tail)
    for (int ch = 0; ch < 9; ch++) {
        __syncthreads();
        // stage W1 chunk (hi + lo), transposed [n][ki]
        {
            const uint4* w1h = (const uint4*)(g_w1hi + (layer * 9 + ch) * 4096);
            const uint4* w1l = (const uint4*)(g_w1lo + (layer * 9 + ch) * 4096);
#pragma unroll
            for (int i = tid; i < 512; i += 256) {
                int n = i >> 2, kq = i & 3;
                *(uint4*)(Wh + n * KWP + kq * 8) = w1h[i];
                *(uint4*)(Wl + n * KWP + kq * 8) = w1l[i];
            }
        }
        // gather A chunk [128][32] bf16
        if (ch < 8) {
            int r = tid >> 1, q = tid & 1;
            int node = (ch < 4) ? s_src[r] : s_dst[r];
            const float4* Xg = (const float4*)(g_x + node * HID + (ch & 3) * 32 + q * 16);
            float4 v0 = Xg[0], v1 = Xg[1], v2 = Xg[2], v3 = Xg[3];
            uint4 o0, o1;
            o0.x = pbf(v0.x, v0.y); o0.y = pbf(v0.z, v0.w);
            o0.z = pbf(v1.x, v1.y); o0.w = pbf(v1.z, v1.w);
            o1.x = pbf(v2.x, v2.y); o1.y = pbf(v2.z, v2.w);
            o1.z = pbf(v3.x, v3.y); o1.w = pbf(v3.z, v3.w);
            *(uint4*)(As + r * KWP + q * 16) = o0;
            *(uint4*)(As + r * KWP + q * 16 + 8) = o1;
        } else if (tid < 128) {
            float4 v = ((const float4*)ea)[e0 + tid];
            uint4 o;
            o.x = pbf(v.x, v.y); o.y = pbf(v.z, v.w); o.z = 0u; o.w = 0u;
            uint4 zz = make_uint4(0u, 0u, 0u, 0u);
            *(uint4*)(As + tid * KWP) = o;
            *(uint4*)(As + tid * KWP + 8) = zz;
            *(uint4*)(As + tid * KWP + 16) = zz;
            *(uint4*)(As + tid * KWP + 24) = zz;
        }
        __syncthreads();

        const int nks = (ch == 8) ? 1 : 2;
        for (int ks = 0; ks < nks; ks++) {
            uint32_t a[2][4];
#pragma unroll
            for (int mi = 0; mi < 2; mi++) {
                const __nv_bfloat16* ap = As + (wm * 32 + mi * 16 + g) * KWP + ks * 16 + 2 * t;
                a[mi][0] = *(const uint32_t*)ap;
                a[mi][1] = *(const uint32_t*)(ap + 8 * KWP);
                a[mi][2] = *(const uint32_t*)(ap + 8);
                a[mi][3] = *(const uint32_t*)(ap + 8 * KWP + 8);
            }
#pragma unroll
            for (int ni = 0; ni < 8; ni++) {
                int n = wn * 64 + ni * 8 + g;
                const __nv_bfloat16* wph = Wh + n * KWP + ks * 16 + 2 * t;
                const __nv_bfloat16* wpl = Wl + n * KWP + ks * 16 + 2 * t;
                uint32_t bh0 = *(const uint32_t*)wph;
                uint32_t bh1 = *(const uint32_t*)(wph + 8);
                uint32_t bl0 = *(const uint32_t*)wpl;
                uint32_t bl1 = *(const uint32_t*)(wpl + 8);
                mma16(c[0][ni], a[0], bh0, bh1);
                mma16(c[1][ni], a[1], bh0, bh1);
                mma16(c[0][ni], a[0], bl0, bl1);
                mma16(c[1][ni], a[1], bl0, bl1);
            }
        }
    }

    // ---- epilogue 1: bias + silu -> bf16 H in Hs[128][136]
    __syncthreads();
#pragma unroll
    for (int ni = 0; ni < 8; ni++) {
        int nb = wn * 64 + ni * 8 + 2 * t;
        float bx = s_b1[nb], by = s_b1[nb + 1];
#pragma unroll
        for (int mi = 0; mi < 2; mi++) {
            int r0 = wm * 32 + mi * 16 + g;
            uint32_t p0 = pbf(silu_f(c[mi][ni][0] + bx), silu_f(c[mi][ni][1] + by));
            uint32_t p1 = pbf(silu_f(c[mi][ni][2] + bx), silu_f(c[mi][ni][3] + by));
            *(uint32_t*)(Hs + r0 * HSB + nb) = p0;
            *(uint32_t*)(Hs + (r0 + 8) * HSB + nb) = p1;
            c[mi][ni][0] = c[mi][ni][1] = c[mi][ni][2] = c[mi][ni][3] = 0.0f;
        }
    }

    // ================= GEMM 2: K=128, 4 chunks of 32, A = Hs (bf16)
    for (int ch = 0; ch < 4; ch++) {
        __syncthreads();
        {
            const uint4* w2h = (const uint4*)(g_w2hi + (layer * 4 + ch) * 4096);
            const uint4* w2l = (const uint4*)(g_w2lo + (layer * 4 + ch) * 4096);
#pragma unroll
            for (int i = tid; i < 512; i += 256) {
                int n = i >> 2, kq = i & 3;
                *(uint4*)(Wh + n * KWP + kq * 8) = w2h[i];
                *(uint4*)(Wl + n * KWP + kq * 8) = w2l[i];
            }
        }
        __syncthreads();
#pragma unroll
        for (int ks = 0; ks < 2; ks++) {
            uint32_t a[2][4];
#pragma unroll
            for (int mi = 0; mi < 2; mi++) {
                const __nv_bfloat16* ap = Hs + (wm * 32 + mi * 16 + g) * HSB + ch * 32 + ks * 16 + 2 * t;
                a[mi][0] = *(const uint32_t*)ap;
                a[mi][1] = *(const uint32_t*)(ap + 8 * HSB);
                a[mi][2] = *(const uint32_t*)(ap + 8);
                a[mi][3] = *(const uint32_t*)(ap + 8 * HSB + 8);
            }
#pragma unroll
            for (int ni = 0; ni < 8; ni++) {
                int n = wn * 64 + ni * 8 + g;
                const __nv_bfloat16* wph = Wh + n * KWP + ks * 16 + 2 * t;
                const __nv_bfloat16* wpl = Wl + n * KWP + ks * 16 + 2 * t;
                uint32_t bh0 = *(const uint32_t*)wph;
                uint32_t bh1 = *(const uint32_t*)(wph + 8);
                uint32_t bl0 = *(const uint32_t*)wpl;
                uint32_t bl1 = *(const uint32_t*)(wpl + 8);
                mma16(c[0][ni], a[0], bh0, bh1);
                mma16(c[1][ni], a[1], bh0, bh1);
                mma16(c[0][ni], a[0], bl0, bl1);
                mma16(c[1][ni], a[1], bl0, bl1);
            }
        }
    }

    // ---- epilogue 2: bias + silu, stage fp32 per 64-col half, coalesced scatter
    float* Ms = (float*)Hs;  // [128][68] fp32
#pragma unroll
    for (int h = 0; h < 2; h++) {
        __syncthreads();
        if (wn == h) {
#pragma unroll
            for (int ni = 0; ni < 8; ni++) {
                int nb = ni * 8 + 2 * t;           // local col within half
                float bx = s_b2[h * 64 + nb], by = s_b2[h * 64 + nb + 1];
#pragma unroll
                for (int mi = 0; mi < 2; mi++) {
                    int r0 = wm * 32 + mi * 16 + g;
                    float2 m0, m1;
                    m0.x = silu_f(c[mi][ni][0] + bx);
                    m0.y = silu_f(c[mi][ni][1] + by);
                    m1.x = silu_f(c[mi][ni][2] + bx);
                    m1.y = silu_f(c[mi][ni][3] + by);
                    *(float2*)(Ms + r0 * 68 + nb) = m0;
                    *(float2*)(Ms + (r0 + 8) * 68 + nb) = m1;
                }
            }
        }
        __syncthreads();
#pragma unroll
        for (int i = 0; i < 8; i++) {
            int idx2 = tid + i * 256;
            int row = idx2 >> 4, c4 = idx2 & 15;
            float4 v = *(const float4*)(Ms + row * 68 + c4 * 4);
            atomicAdd((float4*)(g_agg + s_dst[row] * HID + h * 64 + c4 * 4), v);
        }
    }
}

// ---------------------------------------------------------------------------
// node update x = silu(concat(x, agg) @ nw + nb); re-zero agg. (FFMA)
// ---------------------------------------------------------------------------
#define AS_STRIDE 68

__global__ void node_kernel(const float* __restrict__ nw, const float* __restrict__ nb,
                            int layer) {
    extern __shared__ float smn[];
    float* Ws = smn;
    float* As = smn + 64 * 128;
    const int tid = threadIdx.x;
    const int tx = tid & 31, ty = tid >> 5;
    const int n0 = blockIdx.x * 64;
    const float* W = nw + layer * 2 * HID * HID;

    float acc[8][4];
#pragma unroll
    for (int r = 0; r < 8; r++)
#pragma unroll
        for (int c = 0; c < 4; c++) acc[r][c] = 0.0f;

    for (int ch = 0; ch < 4; ch++) {
        __syncthreads();
        const float4* Wg = (const float4*)(W + ch * 64 * HID);
        float4* Ws4 = (float4*)Ws;
#pragma unroll
        for (int t = 0; t < 8; t++) Ws4[tid + t * 256] = Wg[tid + t * 256];
        {
            int row = tid >> 2;
            int q = tid & 3;
            int n = n0 + row;
            const float* base = ((ch < 2) ? g_x : g_agg);
            const float4* Xg = (const float4*)(base + n * HID + (ch & 1) * 64);
            float4* A4 = (float4*)As;
#pragma unroll
            for (int t = 0; t < 4; t++) {
                float4 v = make_float4(0.f, 0.f, 0.f, 0.f);
                if (n < N_NODES) v = Xg[q + t * 4];
                A4[row * 17 + q + t * 4] = v;
            }
        }
        __syncthreads();
#pragma unroll
        for (int k = 0; k < 64; k++) {
            float4 b = ((const float4*)Ws)[k * 32 + tx];
#pragma unroll
            for (int r = 0; r < 8; r++) {
                float a = As[(ty * 8 + r) * AS_STRIDE + k];
                acc[r][0] += a * b.x; acc[r][1] += a * b.y;
                acc[r][2] += a * b.z; acc[r][3] += a * b.w;
            }
        }
    }

    {
        float4 bb = ((const float4*)(nb + layer * HID))[tx];
        float4 z4 = make_float4(0.f, 0.f, 0.f, 0.f);
#pragma unroll
        for (int r = 0; r < 8; r++) {
            int n = n0 + ty * 8 + r;
            if (n < N_NODES) {
                float4 h;
                h.x = silu_f(acc[r][0] + bb.x);
                h.y = silu_f(acc[r][1] + bb.y);
                h.z = silu_f(acc[r][2] + bb.z);
                h.w = silu_f(acc[r][3] + bb.w);
                ((float4*)(g_x + n * HID))[tx] = h;
                ((float4*)(g_agg + n * HID))[tx] = z4;
            }
        }
    }
}

// ---------------------------------------------------------------------------
__global__ void pool_kernel(const int* __restrict__ batch) {
    int idx = blockIdx.x * 256 + threadIdx.x;
    if (idx < N_NODES * 32) {
        int n = idx >> 5, c = idx & 31;
        int b = batch[n];
        float4 v = ((const float4*)g_x)[idx];
        atomicAdd((float4*)(g_gsum + b * HID + c * 4), v);
        if (c == 0) atomicAdd(&g_gcnt[b], 1.0f);
    }
}

__global__ void readout_kernel(const float* __restrict__ rw1, const float* __restrict__ rb1,
                               const float* __restrict__ rw2, const float* __restrict__ rb2,
                               float* __restrict__ out) {
    __shared__ float gsh[HID];
    __shared__ float part[4];
    int g = blockIdx.x, j = threadIdx.x;
    float cnt = fmaxf(g_gcnt[g], 1.0f);
    gsh[j] = g_gsum[g * HID + j] / cnt;
    __syncthreads();
    float s = rb1[j];
#pragma unroll
    for (int k = 0; k < HID; k++) s += gsh[k] * rw1[k * HID + j];
    float v = silu_f(s) * rw2[j];
#pragma unroll
    for (int off = 16; off > 0; off >>= 1) v += __shfl_xor_sync(0xffffffffu, v, off);
    if ((j & 31) == 0) part[j >> 5] = v;
    __syncthreads();
    if (j == 0) out[g] = part[0] + part[1] + part[2] + part[3] + rb2[0];
}

// ---------------------------------------------------------------------------
extern "C" void kernel_launch(void* const* d_in, const int* in_sizes, int n_in,
                              void* d_out, int out_size) {
    const int*   z    = (const int*)d_in[0];
    const int*   ei   = (const int*)d_in[1];
    const float* ea   = (const float*)d_in[2];
    const int*   batch= (const int*)d_in[3];
    const float* emb  = (const float*)d_in[4];
    const float* ew1  = (const float*)d_in[5];
    const float* eb1  = (const float*)d_in[6];
    const float* ew2  = (const float*)d_in[7];
    const float* eb2  = (const float*)d_in[8];
    const float* nw   = (const float*)d_in[9];
    const float* nb   = (const float*)d_in[10];
    const float* rw1  = (const float*)d_in[11];
    const float* rb1  = (const float*)d_in[12];
    const float* rw2  = (const float*)d_in[13];
    const float* rb2  = (const float*)d_in[14];
    float* out = (float*)d_out;

    const int NODE_SMEM = (64 * 128 + 64 * AS_STRIDE) * (int)sizeof(float);
    cudaFuncSetAttribute(edge_tc_kernel, cudaFuncAttributeMaxDynamicSharedMemorySize, EDGE_SMEM);
    cudaFuncSetAttribute(node_kernel, cudaFuncAttributeMaxDynamicSharedMemorySize, NODE_SMEM);

    pack_w_kernel<<<(LAYERS * 9 * 128 * 32 + 255) / 256, 256>>>(ew1, ew2);
    embed_kernel<<<(N_NODES * HID + 255) / 256, 256>>>(z, emb);
    for (int l = 0; l < LAYERS; l++) {
        edge_tc_kernel<<<N_EDGES / 128, 256, EDGE_SMEM>>>(ei, ea, eb1, eb2, l);
        node_kernel<<<(N_NODES + 63) / 64, 256, NODE_SMEM>>>(nw, nb, l);
    }
    pool_kernel<<<(N_NODES * 32 + 255) / 256, 256>>>(batch);
    readout_kernel<<<NUM_GRAPHS, HID>>>(rw1, rb1, rw2, rb2, out);
}

// round 10
// speedup vs baseline: 2.2234x; 1.0633x over previous
#include <cuda_runtime.h>
#include <cuda_bf16.h>
#include <cstdint>

#define N_NODES 50000
#define N_EDGES 800000
#define HID 128
#define EDGE_DIM 4
#define LAYERS 4
#define NUM_GRAPHS 512

// ------------------------- device scratch (no allocs allowed) ---------------
__device__ float g_x[N_NODES * HID];
__device__ float g_agg[N_NODES * HID];
__device__ float g_gsum[NUM_GRAPHS * HID];
__device__ float g_gcnt[NUM_GRAPHS];

// bf16 hi/lo split weights, TRANSPOSED per 32-k chunk: [l][kb][n=128][ki=32]
// W1: K padded 260 -> 288 (9 chunks). W2: 128 (4 chunks). NW: 256 (8 chunks).
__device__ __nv_bfloat16 g_w1hi[LAYERS * 9 * 128 * 32];
__device__ __nv_bfloat16 g_w1lo[LAYERS * 9 * 128 * 32];
__device__ __nv_bfloat16 g_w2hi[LAYERS * 4 * 128 * 32];
__device__ __nv_bfloat16 g_w2lo[LAYERS * 4 * 128 * 32];
__device__ __nv_bfloat16 g_nwhi[LAYERS * 8 * 128 * 32];
__device__ __nv_bfloat16 g_nwlo[LAYERS * 8 * 128 * 32];

__device__ __forceinline__ float silu_f(float v) { return v / (1.0f + __expf(-v)); }

__device__ __forceinline__ uint32_t pbf(float a, float b) {
    __nv_bfloat162 t = __floats2bfloat162_rn(a, b);
    return *(uint32_t*)&t;
}

__device__ __forceinline__ void mma16(float* d, const uint32_t* a, uint32_t b0, uint32_t b1) {
    asm volatile(
        "mma.sync.aligned.m16n8k16.row.col.f32.bf16.bf16.f32 "
        "{%0,%1,%2,%3}, {%4,%5,%6,%7}, {%8,%9}, {%0,%1,%2,%3};"
        : "+f"(d[0]), "+f"(d[1]), "+f"(d[2]), "+f"(d[3])
        : "r"(a[0]), "r"(a[1]), "r"(a[2]), "r"(a[3]), "r"(b0), "r"(b1));
}

__device__ __forceinline__ void ldsm4(uint32_t* r, uint32_t saddr) {
    asm volatile("ldmatrix.sync.aligned.m8n8.x4.shared.b16 {%0,%1,%2,%3}, [%4];"
        : "=r"(r[0]), "=r"(r[1]), "=r"(r[2]), "=r"(r[3]) : "r"(saddr));
}

// ---------------------------------------------------------------------------
// Pack: hi = bf16(w), lo = bf16(w - hi), layout [l][kb][n][ki]
// ---------------------------------------------------------------------------
__global__ void pack_w_kernel(const float* __restrict__ ew1, const float* __restrict__ ew2,
                              const float* __restrict__ nw) {
    int idx = blockIdx.x * 256 + threadIdx.x;
    if (idx < LAYERS * 9 * 128 * 32) {
        int l = idx / (9 * 128 * 32);
        int r = idx % (9 * 128 * 32);
        int kb = r / (128 * 32);
        int r2 = r % (128 * 32);
        int n = r2 >> 5, ki = r2 & 31;
        int kg = kb * 32 + ki;
        float w = (kg < 2 * HID + EDGE_DIM) ? ew1[(l * (2 * HID + EDGE_DIM) + kg) * HID + n] : 0.0f;
        __nv_bfloat16 hi = __float2bfloat16(w);
        __nv_bfloat16 lo = __float2bfloat16(w - __bfloat162float(hi));
        g_w1hi[idx] = hi;
        g_w1lo[idx] = lo;
    }
    if (idx < LAYERS * 4 * 128 * 32) {
        int l = idx / (4 * 128 * 32);
        int r = idx % (4 * 128 * 32);
        int kb = r / (128 * 32);
        int r2 = r % (128 * 32);
        int n = r2 >> 5, ki = r2 & 31;
        int kg = kb * 32 + ki;
        float w = ew2[(l * HID + kg) * HID + n];
        __nv_bfloat16 hi = __float2bfloat16(w);
        __nv_bfloat16 lo = __float2bfloat16(w - __bfloat162float(hi));
        g_w2hi[idx] = hi;
        g_w2lo[idx] = lo;
    }
    if (idx < LAYERS * 8 * 128 * 32) {
        int l = idx / (8 * 128 * 32);
        int r = idx % (8 * 128 * 32);
        int kb = r / (128 * 32);
        int r2 = r % (128 * 32);
        int n = r2 >> 5, ki = r2 & 31;
        int kg = kb * 32 + ki;
        float w = nw[(l * 2 * HID + kg) * HID + n];
        __nv_bfloat16 hi = __float2bfloat16(w);
        __nv_bfloat16 lo = __float2bfloat16(w - __bfloat162float(hi));
        g_nwhi[idx] = hi;
        g_nwlo[idx] = lo;
    }
}

// ---------------------------------------------------------------------------
// embedding lookup + zero scratch
// ---------------------------------------------------------------------------
__global__ void embed_kernel(const int* __restrict__ z, const float* __restrict__ emb) {
    int idx = blockIdx.x * 256 + threadIdx.x;
    if (idx < N_NODES * HID) {
        int n = idx >> 7, j = idx & 127;
        g_x[idx] = emb[z[n] * HID + j];
        g_agg[idx] = 0.0f;
    }
    if (idx < NUM_GRAPHS * HID) g_gsum[idx] = 0.0f;
    if (idx < NUM_GRAPHS) g_gcnt[idx] = 0.0f;
}

// ---------------------------------------------------------------------------
// Edge MLP: bf16 m16n8k16 mma.sync + ldmatrix, hi/lo split weights.
// Block = 128 edges, 256 threads (8 warps). Warp (wm=wid&3, wn=wid>>2)
// owns rows [wm*32,+32) x cols [wn*64,+64).
// smem (bf16): Wh[128][40] | Wl[128][40] | Hs[128][136]  (A[128][40] aliases Hs;
// epilogue2 reuses Hs as float[128][68] per 64-col half)
// ---------------------------------------------------------------------------
#define KWP 40   // W / A bf16 row stride
#define HSB 136  // H bf16 row stride
#define EDGE_SMEM ((2 * 128 * KWP + 128 * HSB) * 2)

__global__ __launch_bounds__(256, 2)
void edge_tc_kernel(const int* __restrict__ ei, const float* __restrict__ ea,
                    const float* __restrict__ eb1, const float* __restrict__ eb2,
                    int layer) {
    extern __shared__ __nv_bfloat16 sm[];
    __nv_bfloat16* Wh = sm;                    // [128][40]
    __nv_bfloat16* Wl = Wh + 128 * KWP;        // [128][40]
    __nv_bfloat16* Hs = Wl + 128 * KWP;        // [128][136]
    __nv_bfloat16* As = Hs;                    // alias: A chunk [128][40]
    __shared__ int s_src[128], s_dst[128];
    __shared__ float s_b1[HID], s_b2[HID];

    const int tid = threadIdx.x;
    const int lane = tid & 31, wid = tid >> 5;
    const int g = lane >> 2, t = lane & 3;
    const int wm = wid & 3, wn = wid >> 2;
    const int e0 = blockIdx.x * 128;

    // ldmatrix per-lane tile geometry
    const int lm = lane & 7, lt = lane >> 3;
    const int a_row = (lt & 1) * 8 + lm, a_k8 = (lt >> 1) * 8;
    const int b_row = (lt >> 1) * 8 + lm, b_k8 = (lt & 1) * 8;

    const uint32_t Wh_u = (uint32_t)__cvta_generic_to_shared(Wh);
    const uint32_t Wl_u = (uint32_t)__cvta_generic_to_shared(Wl);
    const uint32_t Hs_u = (uint32_t)__cvta_generic_to_shared(Hs);

    if (tid < 128) {
        s_src[tid] = ei[e0 + tid];
        s_dst[tid] = ei[N_EDGES + e0 + tid];
        s_b1[tid] = eb1[layer * HID + tid];
        s_b2[tid] = eb2[layer * HID + tid];
    }

    float c[2][8][4];
#pragma unroll
    for (int mi = 0; mi < 2; mi++)
#pragma unroll
        for (int ni = 0; ni < 8; ni++)
#pragma unroll
            for (int q = 0; q < 4; q++) c[mi][ni][q] = 0.0f;

    // ================= GEMM 1: 9 chunks of K=32 (8 data + 1 edge_attr tail)
    for (int ch = 0; ch < 9; ch++) {
        __syncthreads();
        // stage W1 chunk (hi + lo), transposed [n][ki]
        {
            const uint4* w1h = (const uint4*)(g_w1hi + (layer * 9 + ch) * 4096);
            const uint4* w1l = (const uint4*)(g_w1lo + (layer * 9 + ch) * 4096);
#pragma unroll
            for (int i = tid; i < 512; i += 256) {
                int n = i >> 2, kq = i & 3;
                *(uint4*)(Wh + n * KWP + kq * 8) = w1h[i];
                *(uint4*)(Wl + n * KWP + kq * 8) = w1l[i];
            }
        }
        // gather A chunk [128][32] bf16
        if (ch < 8) {
            int r = tid >> 1, q = tid & 1;
            int node = (ch < 4) ? s_src[r] : s_dst[r];
            const float4* Xg = (const float4*)(g_x + node * HID + (ch & 3) * 32 + q * 16);
            float4 v0 = Xg[0], v1 = Xg[1], v2 = Xg[2], v3 = Xg[3];
            uint4 o0, o1;
            o0.x = pbf(v0.x, v0.y); o0.y = pbf(v0.z, v0.w);
            o0.z = pbf(v1.x, v1.y); o0.w = pbf(v1.z, v1.w);
            o1.x = pbf(v2.x, v2.y); o1.y = pbf(v2.z, v2.w);
            o1.z = pbf(v3.x, v3.y); o1.w = pbf(v3.z, v3.w);
            *(uint4*)(As + r * KWP + q * 16) = o0;
            *(uint4*)(As + r * KWP + q * 16 + 8) = o1;
        } else if (tid < 128) {
            float4 v = ((const float4*)ea)[e0 + tid];
            uint4 o;
            o.x = pbf(v.x, v.y); o.y = pbf(v.z, v.w); o.z = 0u; o.w = 0u;
            uint4 zz = make_uint4(0u, 0u, 0u, 0u);
            *(uint4*)(As + tid * KWP) = o;
            *(uint4*)(As + tid * KWP + 8) = zz;
            *(uint4*)(As + tid * KWP + 16) = zz;
            *(uint4*)(As + tid * KWP + 24) = zz;
        }
        __syncthreads();

        const int nks = (ch == 8) ? 1 : 2;
        for (int ks = 0; ks < nks; ks++) {
            uint32_t a[2][4];
            uint32_t ab = Hs_u + 2 * ((wm * 32 + a_row) * KWP + ks * 16 + a_k8);
            ldsm4(a[0], ab);
            ldsm4(a[1], ab + 2 * 16 * KWP);
#pragma unroll
            for (int p = 0; p < 4; p++) {
                uint32_t bh[4], bl[4];
                uint32_t wb = 2 * ((wn * 64 + p * 16 + b_row) * KWP + ks * 16 + b_k8);
                ldsm4(bh, Wh_u + wb);
                ldsm4(bl, Wl_u + wb);
                mma16(c[0][2 * p], a[0], bh[0], bh[1]);
                mma16(c[1][2 * p], a[1], bh[0], bh[1]);
                mma16(c[0][2 * p], a[0], bl[0], bl[1]);
                mma16(c[1][2 * p], a[1], bl[0], bl[1]);
                mma16(c[0][2 * p + 1], a[0], bh[2], bh[3]);
                mma16(c[1][2 * p + 1], a[1], bh[2], bh[3]);
                mma16(c[0][2 * p + 1], a[0], bl[2], bl[3]);
                mma16(c[1][2 * p + 1], a[1], bl[2], bl[3]);
            }
        }
    }

    // ---- epilogue 1: bias + silu -> bf16 H in Hs[128][136]
    __syncthreads();
#pragma unroll
    for (int ni = 0; ni < 8; ni++) {
        int nb = wn * 64 + ni * 8 + 2 * t;
        float bx = s_b1[nb], by = s_b1[nb + 1];
#pragma unroll
        for (int mi = 0; mi < 2; mi++) {
            int r0 = wm * 32 + mi * 16 + g;
            uint32_t p0 = pbf(silu_f(c[mi][ni][0] + bx), silu_f(c[mi][ni][1] + by));
            uint32_t p1 = pbf(silu_f(c[mi][ni][2] + bx), silu_f(c[mi][ni][3] + by));
            *(uint32_t*)(Hs + r0 * HSB + nb) = p0;
            *(uint32_t*)(Hs + (r0 + 8) * HSB + nb) = p1;
            c[mi][ni][0] = c[mi][ni][1] = c[mi][ni][2] = c[mi][ni][3] = 0.0f;
        }
    }

    // ================= GEMM 2: K=128, 4 chunks of 32, A = Hs (bf16)
    for (int ch = 0; ch < 4; ch++) {
        __syncthreads();
        {
            const uint4* w2h = (const uint4*)(g_w2hi + (layer * 4 + ch) * 4096);
            const uint4* w2l = (const uint4*)(g_w2lo + (layer * 4 + ch) * 4096);
#pragma unroll
            for (int i = tid; i < 512; i += 256) {
                int n = i >> 2, kq = i & 3;
                *(uint4*)(Wh + n * KWP + kq * 8) = w2h[i];
                *(uint4*)(Wl + n * KWP + kq * 8) = w2l[i];
            }
        }
        __syncthreads();
#pragma unroll
        for (int ks = 0; ks < 2; ks++) {
            uint32_t a[2][4];
            uint32_t ab = Hs_u + 2 * ((wm * 32 + a_row) * HSB + ch * 32 + ks * 16 + a_k8);
            ldsm4(a[0], ab);
            ldsm4(a[1], ab + 2 * 16 * HSB);
#pragma unroll
            for (int p = 0; p < 4; p++) {
                uint32_t bh[4], bl[4];
                uint32_t wb = 2 * ((wn * 64 + p * 16 + b_row) * KWP + ks * 16 + b_k8);
                ldsm4(bh, Wh_u + wb);
                ldsm4(bl, Wl_u + wb);
                mma16(c[0][2 * p], a[0], bh[0], bh[1]);
                mma16(c[1][2 * p], a[1], bh[0], bh[1]);
                mma16(c[0][2 * p], a[0], bl[0], bl[1]);
                mma16(c[1][2 * p], a[1], bl[0], bl[1]);
                mma16(c[0][2 * p + 1], a[0], bh[2], bh[3]);
                mma16(c[1][2 * p + 1], a[1], bh[2], bh[3]);
                mma16(c[0][2 * p + 1], a[0], bl[2], bl[3]);
                mma16(c[1][2 * p + 1], a[1], bl[2], bl[3]);
            }
        }
    }

    // ---- epilogue 2: bias + silu, stage fp32 per 64-col half, coalesced scatter
    float* Ms = (float*)Hs;  // [128][68] fp32
#pragma unroll
    for (int h = 0; h < 2; h++) {
        __syncthreads();
        if (wn == h) {
#pragma unroll
            for (int ni = 0; ni < 8; ni++) {
                int nb = ni * 8 + 2 * t;           // local col within half
                float bx = s_b2[h * 64 + nb], by = s_b2[h * 64 + nb + 1];
#pragma unroll
                for (int mi = 0; mi < 2; mi++) {
                    int r0 = wm * 32 + mi * 16 + g;
                    float2 m0, m1;
                    m0.x = silu_f(c[mi][ni][0] + bx);
                    m0.y = silu_f(c[mi][ni][1] + by);
                    m1.x = silu_f(c[mi][ni][2] + bx);
                    m1.y = silu_f(c[mi][ni][3] + by);
                    *(float2*)(Ms + r0 * 68 + nb) = m0;
                    *(float2*)(Ms + (r0 + 8) * 68 + nb) = m1;
                }
            }
        }
        __syncthreads();
#pragma unroll
        for (int i = 0; i < 8; i++) {
            int idx2 = tid + i * 256;
            int row = idx2 >> 4, c4 = idx2 & 15;
            float4 v = *(const float4*)(Ms + row * 68 + c4 * 4);
            atomicAdd((float4*)(g_agg + s_dst[row] * HID + h * 64 + c4 * 4), v);
        }
    }
}

// ---------------------------------------------------------------------------
// Node update on tensor cores: x = silu(concat(x, agg) @ nw + nb); re-zero agg.
// Block = 128 nodes, 256 threads, same fragment scheme as edge kernel.
// ---------------------------------------------------------------------------
__global__ __launch_bounds__(256, 2)
void node_tc_kernel(const float* __restrict__ nbv, int layer) {
    extern __shared__ __nv_bfloat16 sm[];
    __nv_bfloat16* Wh = sm;
    __nv_bfloat16* Wl = Wh + 128 * KWP;
    __nv_bfloat16* Hs = Wl + 128 * KWP;
    __nv_bfloat16* As = Hs;
    __shared__ float s_nb[HID];

    const int tid = threadIdx.x;
    const int lane = tid & 31, wid = tid >> 5;
    const int g = lane >> 2, t = lane & 3;
    const int wm = wid & 3, wn = wid >> 2;
    const int n0 = blockIdx.x * 128;

    const int lm = lane & 7, lt = lane >> 3;
    const int a_row = (lt & 1) * 8 + lm, a_k8 = (lt >> 1) * 8;
    const int b_row = (lt >> 1) * 8 + lm, b_k8 = (lt & 1) * 8;

    const uint32_t Wh_u = (uint32_t)__cvta_generic_to_shared(Wh);
    const uint32_t Wl_u = (uint32_t)__cvta_generic_to_shared(Wl);
    const uint32_t Hs_u = (uint32_t)__cvta_generic_to_shared(Hs);

    if (tid < 128) s_nb[tid] = nbv[layer * HID + tid];

    float c[2][8][4];
#pragma unroll
    for (int mi = 0; mi < 2; mi++)
#pragma unroll
        for (int ni = 0; ni < 8; ni++)
#pragma unroll
            for (int q = 0; q < 4; q++) c[mi][ni][q] = 0.0f;

    // K = 256 (x || agg) in 8 chunks of 32
    for (int ch = 0; ch < 8; ch++) {
        __syncthreads();
        {
            const uint4* wh = (const uint4*)(g_nwhi + (layer * 8 + ch) * 4096);
            const uint4* wl = (const uint4*)(g_nwlo + (layer * 8 + ch) * 4096);
#pragma unroll
            for (int i = tid; i < 512; i += 256) {
                int n = i >> 2, kq = i & 3;
                *(uint4*)(Wh + n * KWP + kq * 8) = wh[i];
                *(uint4*)(Wl + n * KWP + kq * 8) = wl[i];
            }
        }
        {
            int r = tid >> 1, q = tid & 1;
            int node = n0 + r;
            uint4 o0 = make_uint4(0u, 0u, 0u, 0u), o1 = o0;
            if (node < N_NODES) {
                const float* base = (ch < 4) ? g_x : g_agg;
                const float4* Xg = (const float4*)(base + node * HID + (ch & 3) * 32 + q * 16);
                float4 v0 = Xg[0], v1 = Xg[1], v2 = Xg[2], v3 = Xg[3];
                o0.x = pbf(v0.x, v0.y); o0.y = pbf(v0.z, v0.w);
                o0.z = pbf(v1.x, v1.y); o0.w = pbf(v1.z, v1.w);
                o1.x = pbf(v2.x, v2.y); o1.y = pbf(v2.z, v2.w);
                o1.z = pbf(v3.x, v3.y); o1.w = pbf(v3.z, v3.w);
            }
            *(uint4*)(As + r * KWP + q * 16) = o0;
            *(uint4*)(As + r * KWP + q * 16 + 8) = o1;
        }
        __syncthreads();
#pragma unroll
        for (int ks = 0; ks < 2; ks++) {
            uint32_t a[2][4];
            uint32_t ab = Hs_u + 2 * ((wm * 32 + a_row) * KWP + ks * 16 + a_k8);
            ldsm4(a[0], ab);
            ldsm4(a[1], ab + 2 * 16 * KWP);
#pragma unroll
            for (int p = 0; p < 4; p++) {
                uint32_t bh[4], bl[4];
                uint32_t wb = 2 * ((wn * 64 + p * 16 + b_row) * KWP + ks * 16 + b_k8);
                ldsm4(bh, Wh_u + wb);
                ldsm4(bl, Wl_u + wb);
                mma16(c[0][2 * p], a[0], bh[0], bh[1]);
                mma16(c[1][2 * p], a[1], bh[0], bh[1]);
                mma16(c[0][2 * p], a[0], bl[0], bl[1]);
                mma16(c[1][2 * p], a[1], bl[0], bl[1]);
                mma16(c[0][2 * p + 1], a[0], bh[2], bh[3]);
                mma16(c[1][2 * p + 1], a[1], bh[2], bh[3]);
                mma16(c[0][2 * p + 1], a[0], bl[2], bl[3]);
                mma16(c[1][2 * p + 1], a[1], bl[2], bl[3]);
            }
        }
    }

    // epilogue: bias + silu, stage per half, coalesced store to g_x; zero agg
    float* Ms = (float*)Hs;  // [128][68]
#pragma unroll
    for (int h = 0; h < 2; h++) {
        __syncthreads();
        if (wn == h) {
#pragma unroll
            for (int ni = 0; ni < 8; ni++) {
                int nb = ni * 8 + 2 * t;
                float bx = s_nb[h * 64 + nb], by = s_nb[h * 64 + nb + 1];
#pragma unroll
                for (int mi = 0; mi < 2; mi++) {
                    int r0 = wm * 32 + mi * 16 + g;
                    float2 m0, m1;
                    m0.x = silu_f(c[mi][ni][0] + bx);
                    m0.y = silu_f(c[mi][ni][1] + by);
                    m1.x = silu_f(c[mi][ni][2] + bx);
                    m1.y = silu_f(c[mi][ni][3] + by);
                    *(float2*)(Ms + r0 * 68 + nb) = m0;
                    *(float2*)(Ms + (r0 + 8) * 68 + nb) = m1;
                }
            }
        }
        __syncthreads();
        float4 z4 = make_float4(0.f, 0.f, 0.f, 0.f);
#pragma unroll
        for (int i = 0; i < 8; i++) {
            int idx2 = tid + i * 256;
            int row = idx2 >> 4, c4 = idx2 & 15;
            int node = n0 + row;
            if (node < N_NODES) {
                float4 v = *(const float4*)(Ms + row * 68 + c4 * 4);
                *(float4*)(g_x + node * HID + h * 64 + c4 * 4) = v;
                *(float4*)(g_agg + node * HID + h * 64 + c4 * 4) = z4;
            }
        }
    }
}

// ---------------------------------------------------------------------------
__global__ void pool_kernel(const int* __restrict__ batch) {
    int idx = blockIdx.x * 256 + threadIdx.x;
    if (idx < N_NODES * 32) {
        int n = idx >> 5, c = idx & 31;
        int b = batch[n];
        float4 v = ((const float4*)g_x)[idx];
        atomicAdd((float4*)(g_gsum + b * HID + c * 4), v);
        if (c == 0) atomicAdd(&g_gcnt[b], 1.0f);
    }
}

__global__ void readout_kernel(const float* __restrict__ rw1, const float* __restrict__ rb1,
                               const float* __restrict__ rw2, const float* __restrict__ rb2,
                               float* __restrict__ out) {
    __shared__ float gsh[HID];
    __shared__ float part[4];
    int g = blockIdx.x, j = threadIdx.x;
    float cnt = fmaxf(g_gcnt[g], 1.0f);
    gsh[j] = g_gsum[g * HID + j] / cnt;
    __syncthreads();
    float s = rb1[j];
#pragma unroll
    for (int k = 0; k < HID; k++) s += gsh[k] * rw1[k * HID + j];
    float v = silu_f(s) * rw2[j];
#pragma unroll
    for (int off = 16; off > 0; off >>= 1) v += __shfl_xor_sync(0xffffffffu, v, off);
    if ((j & 31) == 0) part[j >> 5] = v;
    __syncthreads();
    if (j == 0) out[g] = part[0] + part[1] + part[2] + part[3] + rb2[0];
}

// ---------------------------------------------------------------------------
extern "C" void kernel_launch(void* const* d_in, const int* in_sizes, int n_in,
                              void* d_out, int out_size) {
    const int*   z    = (const int*)d_in[0];
    const int*   ei   = (const int*)d_in[1];
    const float* ea   = (const float*)d_in[2];
    const int*   batch= (const int*)d_in[3];
    const float* emb  = (const float*)d_in[4];
    const float* ew1  = (const float*)d_in[5];
    const float* eb1  = (const float*)d_in[6];
    const float* ew2  = (const float*)d_in[7];
    const float* eb2  = (const float*)d_in[8];
    const float* nw   = (const float*)d_in[9];
    const float* nb   = (const float*)d_in[10];
    const float* rw1  = (const float*)d_in[11];
    const float* rb1  = (const float*)d_in[12];
    const float* rw2  = (const float*)d_in[13];
    const float* rb2  = (const float*)d_in[14];
    float* out = (float*)d_out;

    cudaFuncSetAttribute(edge_tc_kernel, cudaFuncAttributeMaxDynamicSharedMemorySize, EDGE_SMEM);
    cudaFuncSetAttribute(node_tc_kernel, cudaFuncAttributeMaxDynamicSharedMemorySize, EDGE_SMEM);

    pack_w_kernel<<<(LAYERS * 9 * 128 * 32 + 255) / 256, 256>>>(ew1, ew2, nw);
    embed_kernel<<<(N_NODES * HID + 255) / 256, 256>>>(z, emb);
    for (int l = 0; l < LAYERS; l++) {
        edge_tc_kernel<<<N_EDGES / 128, 256, EDGE_SMEM>>>(ei, ea, eb1, eb2, l);
        node_tc_kernel<<<(N_NODES + 127) / 128, 256, EDGE_SMEM>>>(nb, l);
    }
    pool_kernel<<<(N_NODES * 32 + 255) / 256, 256>>>(batch);
    readout_kernel<<<NUM_GRAPHS, HID>>>(rw1, rb1, rw2, rb2, out);
}

// round 12
// speedup vs baseline: 2.4687x; 1.1103x over previous
#include <cuda_runtime.h>
#include <cuda_bf16.h>
#include <cstdint>

#define N_NODES 50000
#define N_EDGES 800000
#define HID 128
#define EDGE_DIM 4
#define LAYERS 4
#define NUM_GRAPHS 512

// ------------------------- device scratch (no allocs allowed) ---------------
__device__ float g_x[N_NODES * HID];
__device__ float g_agg[N_NODES * HID];
__device__ float g_gsum[NUM_GRAPHS * HID];
__device__ float g_gcnt[NUM_GRAPHS];
__device__ __nv_bfloat16 g_xb[N_NODES * HID];     // bf16 mirror of g_x
__device__ __nv_bfloat16 g_eab[N_EDGES * 16];     // edge_attr padded to 16 cols

// bf16 hi/lo split weights, TRANSPOSED per 32-k chunk: [l][kb][n=128][ki=32]
__device__ __nv_bfloat16 g_w1hi[LAYERS * 9 * 128 * 32];
__device__ __nv_bfloat16 g_w1lo[LAYERS * 9 * 128 * 32];
__device__ __nv_bfloat16 g_w2hi[LAYERS * 4 * 128 * 32];
__device__ __nv_bfloat16 g_w2lo[LAYERS * 4 * 128 * 32];
__device__ __nv_bfloat16 g_nwhi[LAYERS * 8 * 128 * 32];
__device__ __nv_bfloat16 g_nwlo[LAYERS * 8 * 128 * 32];

__device__ __forceinline__ float silu_f(float v) { return v / (1.0f + __expf(-v)); }

__device__ __forceinline__ uint32_t pbf(float a, float b) {
    __nv_bfloat162 t = __floats2bfloat162_rn(a, b);
    return *(uint32_t*)&t;
}

__device__ __forceinline__ void mma16(float* d, const uint32_t* a, uint32_t b0, uint32_t b1) {
    asm volatile(
        "mma.sync.aligned.m16n8k16.row.col.f32.bf16.bf16.f32 "
        "{%0,%1,%2,%3}, {%4,%5,%6,%7}, {%8,%9}, {%0,%1,%2,%3};"
        : "+f"(d[0]), "+f"(d[1]), "+f"(d[2]), "+f"(d[3])
        : "r"(a[0]), "r"(a[1]), "r"(a[2]), "r"(a[3]), "r"(b0), "r"(b1));
}

__device__ __forceinline__ void ldsm4(uint32_t* r, uint32_t saddr) {
    asm volatile("ldmatrix.sync.aligned.m8n8.x4.shared.b16 {%0,%1,%2,%3}, [%4];"
        : "=r"(r[0]), "=r"(r[1]), "=r"(r[2]), "=r"(r[3]) : "r"(saddr));
}

__device__ __forceinline__ void cpa16(uint32_t dst, const void* src) {
    asm volatile("cp.async.cg.shared.global [%0], [%1], 16;" :: "r"(dst), "l"(src));
}
#define CPA_COMMIT() asm volatile("cp.async.commit_group;" ::: "memory")
#define CPA_WAIT(n)  asm volatile("cp.async.wait_group %0;" :: "n"(n) : "memory")

// ---------------------------------------------------------------------------
// Pack: hi = bf16(w), lo = bf16(w - hi), layout [l][kb][n][ki]
// ---------------------------------------------------------------------------
__global__ void pack_w_kernel(const float* __restrict__ ew1, const float* __restrict__ ew2,
                              const float* __restrict__ nw) {
    int idx = blockIdx.x * 256 + threadIdx.x;
    if (idx < LAYERS * 9 * 128 * 32) {
        int l = idx / (9 * 128 * 32);
        int r = idx % (9 * 128 * 32);
        int kb = r / (128 * 32);
        int r2 = r % (128 * 32);
        int n = r2 >> 5, ki = r2 & 31;
        int kg = kb * 32 + ki;
        float w = (kg < 2 * HID + EDGE_DIM) ? ew1[(l * (2 * HID + EDGE_DIM) + kg) * HID + n] : 0.0f;
        __nv_bfloat16 hi = __float2bfloat16(w);
        __nv_bfloat16 lo = __float2bfloat16(w - __bfloat162float(hi));
        g_w1hi[idx] = hi;
        g_w1lo[idx] = lo;
    }
    if (idx < LAYERS * 4 * 128 * 32) {
        int l = idx / (4 * 128 * 32);
        int r = idx % (4 * 128 * 32);
        int kb = r / (128 * 32);
        int r2 = r % (128 * 32);
        int n = r2 >> 5, ki = r2 & 31;
        int kg = kb * 32 + ki;
        float w = ew2[(l * HID + kg) * HID + n];
        __nv_bfloat16 hi = __float2bfloat16(w);
        __nv_bfloat16 lo = __float2bfloat16(w - __bfloat162float(hi));
        g_w2hi[idx] = hi;
        g_w2lo[idx] = lo;
    }
    if (idx < LAYERS * 8 * 128 * 32) {
        int l = idx / (8 * 128 * 32);
        int r = idx % (8 * 128 * 32);
        int kb = r / (128 * 32);
        int r2 = r % (128 * 32);
        int n = r2 >> 5, ki = r2 & 31;
        int kg = kb * 32 + ki;
        float w = nw[(l * 2 * HID + kg) * HID + n];
        __nv_bfloat16 hi = __float2bfloat16(w);
        __nv_bfloat16 lo = __float2bfloat16(w - __bfloat162float(hi));
        g_nwhi[idx] = hi;
        g_nwlo[idx] = lo;
    }
}

// ---------------------------------------------------------------------------
// edge_attr pack: 16-col bf16 rows (4 data + 12 zero)
// ---------------------------------------------------------------------------
__global__ void ea_pack_kernel(const float* __restrict__ ea) {
    int e = blockIdx.x * 256 + threadIdx.x;
    if (e < N_EDGES) {
        float4 v = ((const float4*)ea)[e];
        uint4 o;
        o.x = pbf(v.x, v.y); o.y = pbf(v.z, v.w); o.z = 0u; o.w = 0u;
        ((uint4*)g_eab)[e * 2] = o;
        ((uint4*)g_eab)[e * 2 + 1] = make_uint4(0u, 0u, 0u, 0u);
    }
}

// ---------------------------------------------------------------------------
// embedding lookup + zero scratch (+ bf16 mirror)
// ---------------------------------------------------------------------------
__global__ void embed_kernel(const int* __restrict__ z, const float* __restrict__ emb) {
    int idx = blockIdx.x * 256 + threadIdx.x;
    if (idx < N_NODES * HID) {
        int n = idx >> 7, j = idx & 127;
        float v = emb[z[n] * HID + j];
        g_x[idx] = v;
        g_xb[idx] = __float2bfloat16(v);
        g_agg[idx] = 0.0f;
    }
    if (idx < NUM_GRAPHS * HID) g_gsum[idx] = 0.0f;
    if (idx < NUM_GRAPHS) g_gcnt[idx] = 0.0f;
}

// ---------------------------------------------------------------------------
// Edge MLP: bf16 m16n8k16 + ldmatrix + cp.async double-buffered staging.
// Block = 128 edges, 256 threads (8 warps). Warp (wm=wid&3, wn=wid>>2).
// smem: stage[2] x { Wh[128][40] | Wl[128][40] | As[128][40] } | Hs[128][136]
// ---------------------------------------------------------------------------
#define KWP 40
#define HSB 136
#define STGB (3 * 128 * KWP)                       // bf16 per stage buffer
#define EDGE_SMEM ((2 * STGB + 128 * HSB) * 2)     // 96256 bytes

__global__ __launch_bounds__(256, 2)
void edge_tc_kernel(const int* __restrict__ ei,
                    const float* __restrict__ eb1, const float* __restrict__ eb2,
                    int layer) {
    extern __shared__ __nv_bfloat16 sm[];
    __nv_bfloat16* Hs = sm + 2 * STGB;
    __shared__ int s_src[128], s_dst[128];
    __shared__ float s_b1[HID], s_b2[HID];

    const int tid = threadIdx.x;
    const int lane = tid & 31, wid = tid >> 5;
    const int g = lane >> 2, t = lane & 3;
    const int wm = wid & 3, wn = wid >> 2;
    const int e0 = blockIdx.x * 128;

    const int lm = lane & 7, lt = lane >> 3;
    const int a_row = (lt & 1) * 8 + lm, a_k8 = (lt >> 1) * 8;
    const int b_row = (lt >> 1) * 8 + lm, b_k8 = (lt & 1) * 8;

    const uint32_t sm_u = (uint32_t)__cvta_generic_to_shared(sm);
    const uint32_t Hs_u = sm_u + 2 * STGB * 2;
    const int pr = tid >> 1, pq = tid & 1;   // prefetch row / quarter

    if (tid < 128) {
        s_src[tid] = ei[e0 + tid];
        s_dst[tid] = ei[N_EDGES + e0 + tid];
        s_b1[tid] = eb1[layer * HID + tid];
        s_b2[tid] = eb2[layer * HID + tid];
    }
    __syncthreads();

    float c[2][8][4];
#pragma unroll
    for (int mi = 0; mi < 2; mi++)
#pragma unroll
        for (int ni = 0; ni < 8; ni++)
#pragma unroll
            for (int q = 0; q < 4; q++) c[mi][ni][q] = 0.0f;

    // ---- prefetch helpers (macro-free inline lambdas)
    auto pf1 = [&](int ch) {
        uint32_t b_u = sm_u + (ch & 1) * STGB * 2;
        const uint4* w1h = (const uint4*)(g_w1hi + (layer * 9 + ch) * 4096);
        const uint4* w1l = (const uint4*)(g_w1lo + (layer * 9 + ch) * 4096);
#pragma unroll
        for (int i = tid; i < 512; i += 256) {
            int n = i >> 2, kq = i & 3;
            cpa16(b_u + 2 * (n * KWP + kq * 8), w1h + i);
            cpa16(b_u + 2 * (128 * KWP + n * KWP + kq * 8), w1l + i);
        }
        uint32_t adst = b_u + 2 * (2 * 128 * KWP + pr * KWP);
        if (ch < 8) {
            int node = (ch < 4) ? s_src[pr] : s_dst[pr];
            const __nv_bfloat16* srcp = g_xb + node * HID + (ch & 3) * 32 + pq * 16;
            cpa16(adst + 2 * (pq * 16), srcp);
            cpa16(adst + 2 * (pq * 16 + 8), srcp + 8);
        } else {
            cpa16(adst + 2 * (pq * 8), g_eab + (e0 + pr) * 16 + pq * 8);
        }
    };
    auto pf2 = [&](int ch) {
        uint32_t b_u = sm_u + ((ch + 1) & 1) * STGB * 2;
        const uint4* w2h = (const uint4*)(g_w2hi + (layer * 4 + ch) * 4096);
        const uint4* w2l = (const uint4*)(g_w2lo + (layer * 4 + ch) * 4096);
#pragma unroll
        for (int i = tid; i < 512; i += 256) {
            int n = i >> 2, kq = i & 3;
            cpa16(b_u + 2 * (n * KWP + kq * 8), w2h + i);
            cpa16(b_u + 2 * (128 * KWP + n * KWP + kq * 8), w2l + i);
        }
    };

    // ================= GEMM 1: 9 chunks of K=32 (8 data + edge_attr tail)
    pf1(0); CPA_COMMIT();
    for (int ch = 0; ch < 9; ch++) {
        if (ch < 8) { pf1(ch + 1); CPA_COMMIT(); CPA_WAIT(1); }
        else        { CPA_WAIT(0); }
        __syncthreads();
        uint32_t b_u = sm_u + (ch & 1) * STGB * 2;
        uint32_t WhU = b_u, WlU = b_u + 2 * 128 * KWP, AU = b_u + 2 * 2 * 128 * KWP;
        const int nks = (ch == 8) ? 1 : 2;
        for (int ks = 0; ks < nks; ks++) {
            uint32_t a[2][4];
            uint32_t ab = AU + 2 * ((wm * 32 + a_row) * KWP + ks * 16 + a_k8);
            ldsm4(a[0], ab);
            ldsm4(a[1], ab + 2 * 16 * KWP);
#pragma unroll
            for (int p = 0; p < 4; p++) {
                uint32_t bh[4], bl[4];
                uint32_t wb = 2 * ((wn * 64 + p * 16 + b_row) * KWP + ks * 16 + b_k8);
                ldsm4(bh, WhU + wb);
                ldsm4(bl, WlU + wb);
                mma16(c[0][2 * p], a[0], bh[0], bh[1]);
                mma16(c[1][2 * p], a[1], bh[0], bh[1]);
                mma16(c[0][2 * p], a[0], bl[0], bl[1]);
                mma16(c[1][2 * p], a[1], bl[0], bl[1]);
                mma16(c[0][2 * p + 1], a[0], bh[2], bh[3]);
                mma16(c[1][2 * p + 1], a[1], bh[2], bh[3]);
                mma16(c[0][2 * p + 1], a[0], bl[2], bl[3]);
                mma16(c[1][2 * p + 1], a[1], bl[2], bl[3]);
            }
        }
        __syncthreads();
    }

    // ---- prefetch W2 chunk 0 while epilogue 1 runs
    pf2(0); CPA_COMMIT();

    // ---- epilogue 1: bias + silu -> bf16 H in Hs[128][136]
#pragma unroll
    for (int ni = 0; ni < 8; ni++) {
        int nb = wn * 64 + ni * 8 + 2 * t;
        float bx = s_b1[nb], by = s_b1[nb + 1];
#pragma unroll
        for (int mi = 0; mi < 2; mi++) {
            int r0 = wm * 32 + mi * 16 + g;
            uint32_t p0 = pbf(silu_f(c[mi][ni][0] + bx), silu_f(c[mi][ni][1] + by));
            uint32_t p1 = pbf(silu_f(c[mi][ni][2] + bx), silu_f(c[mi][ni][3] + by));
            *(uint32_t*)(Hs + r0 * HSB + nb) = p0;
            *(uint32_t*)(Hs + (r0 + 8) * HSB + nb) = p1;
            c[mi][ni][0] = c[mi][ni][1] = c[mi][ni][2] = c[mi][ni][3] = 0.0f;
        }
    }

    // ================= GEMM 2: K=128, 4 chunks of 32, A = Hs (bf16)
    for (int ch = 0; ch < 4; ch++) {
        if (ch < 3) { pf2(ch + 1); CPA_COMMIT(); CPA_WAIT(1); }
        else        { CPA_WAIT(0); }
        __syncthreads();
        uint32_t b_u = sm_u + ((ch + 1) & 1) * STGB * 2;
        uint32_t WhU = b_u, WlU = b_u + 2 * 128 * KWP;
#pragma unroll
        for (int ks = 0; ks < 2; ks++) {
            uint32_t a[2][4];
            uint32_t ab = Hs_u + 2 * ((wm * 32 + a_row) * HSB + ch * 32 + ks * 16 + a_k8);
            ldsm4(a[0], ab);
            ldsm4(a[1], ab + 2 * 16 * HSB);
#pragma unroll
            for (int p = 0; p < 4; p++) {
                uint32_t bh[4], bl[4];
                uint32_t wb = 2 * ((wn * 64 + p * 16 + b_row) * KWP + ks * 16 + b_k8);
                ldsm4(bh, WhU + wb);
                ldsm4(bl, WlU + wb);
                mma16(c[0][2 * p], a[0], bh[0], bh[1]);
                mma16(c[1][2 * p], a[1], bh[0], bh[1]);
                mma16(c[0][2 * p], a[0], bl[0], bl[1]);
                mma16(c[1][2 * p], a[1], bl[0], bl[1]);
                mma16(c[0][2 * p + 1], a[0], bh[2], bh[3]);
                mma16(c[1][2 * p + 1], a[1], bh[2], bh[3]);
                mma16(c[0][2 * p + 1], a[0], bl[2], bl[3]);
                mma16(c[1][2 * p + 1], a[1], bl[2], bl[3]);
            }
        }
        __syncthreads();
    }

    // ---- epilogue 2: bias + silu, stage fp32 per 64-col half, coalesced scatter
    float* Ms = (float*)Hs;  // [128][68] fp32
#pragma unroll
    for (int h = 0; h < 2; h++) {
        __syncthreads();
        if (wn == h) {
#pragma unroll
            for (int ni = 0; ni < 8; ni++) {
                int nb = ni * 8 + 2 * t;
                float bx = s_b2[h * 64 + nb], by = s_b2[h * 64 + nb + 1];
#pragma unroll
                for (int mi = 0; mi < 2; mi++) {
                    int r0 = wm * 32 + mi * 16 + g;
                    float2 m0, m1;
                    m0.x = silu_f(c[mi][ni][0] + bx);
                    m0.y = silu_f(c[mi][ni][1] + by);
                    m1.x = silu_f(c[mi][ni][2] + bx);
                    m1.y = silu_f(c[mi][ni][3] + by);
                    *(float2*)(Ms + r0 * 68 + nb) = m0;
                    *(float2*)(Ms + (r0 + 8) * 68 + nb) = m1;
                }
            }
        }
        __syncthreads();
#pragma unroll
        for (int i = 0; i < 8; i++) {
            int idx2 = tid + i * 256;
            int row = idx2 >> 4, c4 = idx2 & 15;
            float4 v = *(const float4*)(Ms + row * 68 + c4 * 4);
            atomicAdd((float4*)(g_agg + s_dst[row] * HID + h * 64 + c4 * 4), v);
        }
    }
}

// ---------------------------------------------------------------------------
// Node update on tensor cores with cp.async pipeline.
// Block = 128 nodes, 256 threads. x chunks via cp.async from g_xb; agg chunks
// manual fp32->bf16.
// ---------------------------------------------------------------------------
__global__ __launch_bounds__(256, 2)
void node_tc_kernel(const float* __restrict__ nbv, int layer) {
    extern __shared__ __nv_bfloat16 sm[];
    __nv_bfloat16* Hs = sm + 2 * STGB;
    __shared__ float s_nb[HID];

    const int tid = threadIdx.x;
    const int lane = tid & 31, wid = tid >> 5;
    const int g = lane >> 2, t = lane & 3;
    const int wm = wid & 3, wn = wid >> 2;
    const int n0 = blockIdx.x * 128;

    const int lm = lane & 7, lt = lane >> 3;
    const int a_row = (lt & 1) * 8 + lm, a_k8 = (lt >> 1) * 8;
    const int b_row = (lt >> 1) * 8 + lm, b_k8 = (lt & 1) * 8;

    const uint32_t sm_u = (uint32_t)__cvta_generic_to_shared(sm);
    const int pr = tid >> 1, pq = tid & 1;

    if (tid < 128) s_nb[tid] = nbv[layer * HID + tid];
    __syncthreads();

    float c[2][8][4];
#pragma unroll
    for (int mi = 0; mi < 2; mi++)
#pragma unroll
        for (int ni = 0; ni < 8; ni++)
#pragma unroll
            for (int q = 0; q < 4; q++) c[mi][ni][q] = 0.0f;

    auto pfN = [&](int ch) {
        uint32_t b_u = sm_u + (ch & 1) * STGB * 2;
        const uint4* wh = (const uint4*)(g_nwhi + (layer * 8 + ch) * 4096);
        const uint4* wl = (const uint4*)(g_nwlo + (layer * 8 + ch) * 4096);
#pragma unroll
        for (int i = tid; i < 512; i += 256) {
            int n = i >> 2, kq = i & 3;
            cpa16(b_u + 2 * (n * KWP + kq * 8), wh + i);
            cpa16(b_u + 2 * (128 * KWP + n * KWP + kq * 8), wl + i);
        }
        int node = n0 + pr;
        uint32_t adst = b_u + 2 * (2 * 128 * KWP + pr * KWP);
        __nv_bfloat16* adst_p = sm + (ch & 1) * STGB + 2 * 128 * KWP + pr * KWP;
        if (ch < 4) {
            if (node < N_NODES) {
                const __nv_bfloat16* srcp = g_xb + node * HID + (ch & 3) * 32 + pq * 16;
                cpa16(adst + 2 * (pq * 16), srcp);
                cpa16(adst + 2 * (pq * 16 + 8), srcp + 8);
            } else {
                uint4 zz = make_uint4(0u, 0u, 0u, 0u);
                *(uint4*)(adst_p + pq * 16) = zz;
                *(uint4*)(adst_p + pq * 16 + 8) = zz;
            }
        } else {
            uint4 o0 = make_uint4(0u, 0u, 0u, 0u), o1 = o0;
            if (node < N_NODES) {
                const float4* Xg = (const float4*)(g_agg + node * HID + (ch & 3) * 32 + pq * 16);
                float4 v0 = Xg[0], v1 = Xg[1], v2 = Xg[2], v3 = Xg[3];
                o0.x = pbf(v0.x, v0.y); o0.y = pbf(v0.z, v0.w);
                o0.z = pbf(v1.x, v1.y); o0.w = pbf(v1.z, v1.w);
                o1.x = pbf(v2.x, v2.y); o1.y = pbf(v2.z, v2.w);
                o1.z = pbf(v3.x, v3.y); o1.w = pbf(v3.z, v3.w);
            }
            *(uint4*)(adst_p + pq * 16) = o0;
            *(uint4*)(adst_p + pq * 16 + 8) = o1;
        }
    };

    pfN(0); CPA_COMMIT();
    for (int ch = 0; ch < 8; ch++) {
        if (ch < 7) { pfN(ch + 1); CPA_COMMIT(); CPA_WAIT(1); }
        else        { CPA_WAIT(0); }
        __syncthreads();
        uint32_t b_u = sm_u + (ch & 1) * STGB * 2;
        uint32_t WhU = b_u, WlU = b_u + 2 * 128 * KWP, AU = b_u + 2 * 2 * 128 * KWP;
#pragma unroll
        for (int ks = 0; ks < 2; ks++) {
            uint32_t a[2][4];
            uint32_t ab = AU + 2 * ((wm * 32 + a_row) * KWP + ks * 16 + a_k8);
            ldsm4(a[0], ab);
            ldsm4(a[1], ab + 2 * 16 * KWP);
#pragma unroll
            for (int p = 0; p < 4; p++) {
                uint32_t bh[4], bl[4];
                uint32_t wb = 2 * ((wn * 64 + p * 16 + b_row) * KWP + ks * 16 + b_k8);
                ldsm4(bh, WhU + wb);
                ldsm4(bl, WlU + wb);
                mma16(c[0][2 * p], a[0], bh[0], bh[1]);
                mma16(c[1][2 * p], a[1], bh[0], bh[1]);
                mma16(c[0][2 * p], a[0], bl[0], bl[1]);
                mma16(c[1][2 * p], a[1], bl[0], bl[1]);
                mma16(c[0][2 * p + 1], a[0], bh[2], bh[3]);
                mma16(c[1][2 * p + 1], a[1], bh[2], bh[3]);
                mma16(c[0][2 * p + 1], a[0], bl[2], bl[3]);
                mma16(c[1][2 * p + 1], a[1], bl[2], bl[3]);
            }
        }
        __syncthreads();
    }

    // epilogue: bias + silu, stage per half, store g_x + g_xb, zero agg
    float* Ms = (float*)Hs;  // [128][68]
#pragma unroll
    for (int h = 0; h < 2; h++) {
        __syncthreads();
        if (wn == h) {
#pragma unroll
            for (int ni = 0; ni < 8; ni++) {
                int nb = ni * 8 + 2 * t;
                float bx = s_nb[h * 64 + nb], by = s_nb[h * 64 + nb + 1];
#pragma unroll
                for (int mi = 0; mi < 2; mi++) {
                    int r0 = wm * 32 + mi * 16 + g;
                    float2 m0, m1;
                    m0.x = silu_f(c[mi][ni][0] + bx);
                    m0.y = silu_f(c[mi][ni][1] + by);
                    m1.x = silu_f(c[mi][ni][2] + bx);
                    m1.y = silu_f(c[mi][ni][3] + by);
                    *(float2*)(Ms + r0 * 68 + nb) = m0;
                    *(float2*)(Ms + (r0 + 8) * 68 + nb) = m1;
                }
            }
        }
        __syncthreads();
        float4 z4 = make_float4(0.f, 0.f, 0.f, 0.f);
#pragma unroll
        for (int i = 0; i < 8; i++) {
            int idx2 = tid + i * 256;
            int row = idx2 >> 4, c4 = idx2 & 15;
            int node = n0 + row;
            if (node < N_NODES) {
                float4 v = *(const float4*)(Ms + row * 68 + c4 * 4);
                *(float4*)(g_x + node * HID + h * 64 + c4 * 4) = v;
                uint2 bv;
                bv.x = pbf(v.x, v.y);
                bv.y = pbf(v.z, v.w);
                *(uint2*)(g_xb + node * HID + h * 64 + c4 * 4) = bv;
                *(float4*)(g_agg + node * HID + h * 64 + c4 * 4) = z4;
            }
        }
    }
}

// ---------------------------------------------------------------------------
__global__ void pool_kernel(const int* __restrict__ batch) {
    int idx = blockIdx.x * 256 + threadIdx.x;
    if (idx < N_NODES * 32) {
        int n = idx >> 5, c = idx & 31;
        int b = batch[n];
        float4 v = ((const float4*)g_x)[idx];
        atomicAdd((float4*)(g_gsum + b * HID + c * 4), v);
        if (c == 0) atomicAdd(&g_gcnt[b], 1.0f);
    }
}

__global__ void readout_kernel(const float* __restrict__ rw1, const float* __restrict__ rb1,
                               const float* __restrict__ rw2, const float* __restrict__ rb2,
                               float* __restrict__ out) {
    __shared__ float gsh[HID];
    __shared__ float part[4];
    int g = blockIdx.x, j = threadIdx.x;
    float cnt = fmaxf(g_gcnt[g], 1.0f);
    gsh[j] = g_gsum[g * HID + j] / cnt;
    __syncthreads();
    float s = rb1[j];
#pragma unroll
    for (int k = 0; k < HID; k++) s += gsh[k] * rw1[k * HID + j];
    float v = silu_f(s) * rw2[j];
#pragma unroll
    for (int off = 16; off > 0; off >>= 1) v += __shfl_xor_sync(0xffffffffu, v, off);
    if ((j & 31) == 0) part[j >> 5] = v;
    __syncthreads();
    if (j == 0) out[g] = part[0] + part[1] + part[2] + part[3] + rb2[0];
}

// ---------------------------------------------------------------------------
extern "C" void kernel_launch(void* const* d_in, const int* in_sizes, int n_in,
                              void* d_out, int out_size) {
    const int*   z    = (const int*)d_in[0];
    const int*   ei   = (const int*)d_in[1];
    const float* ea   = (const float*)d_in[2];
    const int*   batch= (const int*)d_in[3];
    const float* emb  = (const float*)d_in[4];
    const float* ew1  = (const float*)d_in[5];
    const float* eb1  = (const float*)d_in[6];
    const float* ew2  = (const float*)d_in[7];
    const float* eb2  = (const float*)d_in[8];
    const float* nw   = (const float*)d_in[9];
    const float* nb   = (const float*)d_in[10];
    const float* rw1  = (const float*)d_in[11];
    const float* rb1  = (const float*)d_in[12];
    const float* rw2  = (const float*)d_in[13];
    const float* rb2  = (const float*)d_in[14];
    float* out = (float*)d_out;

    cudaFuncSetAttribute(edge_tc_kernel, cudaFuncAttributeMaxDynamicSharedMemorySize, EDGE_SMEM);
    cudaFuncSetAttribute(node_tc_kernel, cudaFuncAttributeMaxDynamicSharedMemorySize, EDGE_SMEM);

    pack_w_kernel<<<(LAYERS * 9 * 128 * 32 + 255) / 256, 256>>>(ew1, ew2, nw);
    ea_pack_kernel<<<(N_EDGES + 255) / 256, 256>>>(ea);
    embed_kernel<<<(N_NODES * HID + 255) / 256, 256>>>(z, emb);
    for (int l = 0; l < LAYERS; l++) {
        edge_tc_kernel<<<N_EDGES / 128, 256, EDGE_SMEM>>>(ei, eb1, eb2, l);
        node_tc_kernel<<<(N_NODES + 127) / 128, 256, EDGE_SMEM>>>(nb, l);
    }
    pool_kernel<<<(N_NODES * 32 + 255) / 256, 256>>>(batch);
    readout_kernel<<<NUM_GRAPHS, HID>>>(rw1, rb1, rw2, rb2, out);
}

// round 17
// speedup vs baseline: 3.1663x; 1.2825x over previous
#include <cuda_runtime.h>
#include <cuda_fp16.h>
#include <cstdint>

#define N_NODES 50000
#define N_EDGES 800000
#define HID 128
#define EDGE_DIM 4
#define LAYERS 4
#define NUM_GRAPHS 512

// ------------------------- device scratch (no allocs allowed) ---------------
__device__ float g_x[N_NODES * HID];
__device__ float g_agg[N_NODES * HID];
__device__ float g_gsum[NUM_GRAPHS * HID];
__device__ float g_gcnt[NUM_GRAPHS];
__device__ __half g_xh[N_NODES * HID];      // fp16 mirror of g_x
__device__ __half g_eah[N_EDGES * 16];      // edge_attr padded to 16 cols, fp16

// fp16 weights, TRANSPOSED per 64-k chunk: [l][kb][n=128][ki=64]
// W1: K padded 260 -> 320 (5 chunks; chunk 4 holds rows 256..319, only 256..259 nonzero)
__device__ __half g_w1h[LAYERS * 5 * 128 * 64];
__device__ __half g_w2h[LAYERS * 2 * 128 * 64];
__device__ __half g_nwh[LAYERS * 4 * 128 * 64];

__device__ __forceinline__ float silu_f(float v) { return v / (1.0f + __expf(-v)); }

__device__ __forceinline__ uint32_t ph2(float a, float b) {
    __half2 t = __floats2half2_rn(a, b);
    return *(uint32_t*)&t;
}

__device__ __forceinline__ void mma16(float* d, const uint32_t* a, uint32_t b0, uint32_t b1) {
    asm volatile(
        "mma.sync.aligned.m16n8k16.row.col.f32.f16.f16.f32 "
        "{%0,%1,%2,%3}, {%4,%5,%6,%7}, {%8,%9}, {%0,%1,%2,%3};"
        : "+f"(d[0]), "+f"(d[1]), "+f"(d[2]), "+f"(d[3])
        : "r"(a[0]), "r"(a[1]), "r"(a[2]), "r"(a[3]), "r"(b0), "r"(b1));
}

__device__ __forceinline__ void ldsm4(uint32_t* r, uint32_t saddr) {
    asm volatile("ldmatrix.sync.aligned.m8n8.x4.shared.b16 {%0,%1,%2,%3}, [%4];"
        : "=r"(r[0]), "=r"(r[1]), "=r"(r[2]), "=r"(r[3]) : "r"(saddr));
}

__device__ __forceinline__ void cpa16(uint32_t dst, const void* src) {
    asm volatile("cp.async.cg.shared.global [%0], [%1], 16;" :: "r"(dst), "l"(src));
}
#define CPA_COMMIT() asm volatile("cp.async.commit_group;" ::: "memory")
#define CPA_WAIT(n)  asm volatile("cp.async.wait_group %0;" :: "n"(n) : "memory")

// ---------------------------------------------------------------------------
// Pack weights to fp16, layout [l][kb64][n][ki]
// ---------------------------------------------------------------------------
__global__ void pack_w_kernel(const float* __restrict__ ew1, const float* __restrict__ ew2,
                              const float* __restrict__ nw) {
    int idx = blockIdx.x * 256 + threadIdx.x;
    if (idx < LAYERS * 5 * 128 * 64) {
        int l = idx / (5 * 128 * 64);
        int r = idx % (5 * 128 * 64);
        int kb = r / (128 * 64);
        int r2 = r % (128 * 64);
        int n = r2 >> 6, ki = r2 & 63;
        int kg = kb * 64 + ki;
        float w = (kg < 2 * HID + EDGE_DIM) ? ew1[(l * (2 * HID + EDGE_DIM) + kg) * HID + n] : 0.0f;
        g_w1h[idx] = __float2half(w);
    }
    if (idx < LAYERS * 2 * 128 * 64) {
        int l = idx / (2 * 128 * 64);
        int r = idx % (2 * 128 * 64);
        int kb = r / (128 * 64);
        int r2 = r % (128 * 64);
        int n = r2 >> 6, ki = r2 & 63;
        int kg = kb * 64 + ki;
        g_w2h[idx] = __float2half(ew2[(l * HID + kg) * HID + n]);
    }
    if (idx < LAYERS * 4 * 128 * 64) {
        int l = idx / (4 * 128 * 64);
        int r = idx % (4 * 128 * 64);
        int kb = r / (128 * 64);
        int r2 = r % (128 * 64);
        int n = r2 >> 6, ki = r2 & 63;
        int kg = kb * 64 + ki;
        g_nwh[idx] = __float2half(nw[(l * 2 * HID + kg) * HID + n]);
    }
}

// ---------------------------------------------------------------------------
__global__ void ea_pack_kernel(const float* __restrict__ ea) {
    int e = blockIdx.x * 256 + threadIdx.x;
    if (e < N_EDGES) {
        float4 v = ((const float4*)ea)[e];
        uint4 o;
        o.x = ph2(v.x, v.y); o.y = ph2(v.z, v.w); o.z = 0u; o.w = 0u;
        ((uint4*)g_eah)[e * 2] = o;
        ((uint4*)g_eah)[e * 2 + 1] = make_uint4(0u, 0u, 0u, 0u);
    }
}

// ---------------------------------------------------------------------------
__global__ void embed_kernel(const int* __restrict__ z, const float* __restrict__ emb) {
    int idx = blockIdx.x * 256 + threadIdx.x;
    if (idx < N_NODES * HID) {
        int n = idx >> 7, j = idx & 127;
        float v = emb[z[n] * HID + j];
        g_x[idx] = v;
        g_xh[idx] = __float2half(v);
        g_agg[idx] = 0.0f;
    }
    if (idx < NUM_GRAPHS * HID) g_gsum[idx] = 0.0f;
    if (idx < NUM_GRAPHS) g_gcnt[idx] = 0.0f;
}

// ---------------------------------------------------------------------------
// Edge MLP: fp16 m16n8k16 + ldmatrix + cp.async, K=64 double-buffered chunks.
// Block = 128 edges, 256 threads (8 warps). Warp (wm=wid&3, wn=wid>>2)
// owns rows [wm*32,+32) x cols [wn*64,+64).
// smem (fp16): stage[2] x { W[128][72] | A[128][72] } | Hs[128][136]
// ---------------------------------------------------------------------------
#define KW2 72    // stage row stride (fp16): 144B; 36 words % 32 = 4 -> ldsm conflict-free
#define HSB 136   // Hs row stride
#define STGH (2 * 128 * KW2)                         // fp16 per stage (W + A)
#define EDGE_SMEM ((2 * STGH + 128 * HSB) * 2)       // 108544 bytes

__global__ __launch_bounds__(256, 2)
void edge_tc_kernel(const int* __restrict__ ei,
                    const float* __restrict__ eb1, const float* __restrict__ eb2,
                    int layer) {
    extern __shared__ __half sm[];
    __half* Hs = sm + 2 * STGH;
    __shared__ int s_src[128], s_dst[128];
    __shared__ float s_b1[HID], s_b2[HID];

    const int tid = threadIdx.x;
    const int lane = tid & 31, wid = tid >> 5;
    const int g = lane >> 2, t = lane & 3;
    const int wm = wid & 3, wn = wid >> 2;
    const int e0 = blockIdx.x * 128;

    const int lm = lane & 7, lt = lane >> 3;
    const int a_row = (lt & 1) * 8 + lm, a_k8 = (lt >> 1) * 8;
    const int b_row = (lt >> 1) * 8 + lm, b_k8 = (lt & 1) * 8;

    const uint32_t sm_u = (uint32_t)__cvta_generic_to_shared(sm);
    const uint32_t Hs_u = sm_u + 2 * STGH * 2;
    const int pr = tid >> 1, pq = tid & 1;

    if (tid < 128) {
        s_src[tid] = ei[e0 + tid];
        s_dst[tid] = ei[N_EDGES + e0 + tid];
        s_b1[tid] = eb1[layer * HID + tid];
        s_b2[tid] = eb2[layer * HID + tid];
    }
    __syncthreads();

    float c[2][8][4];
#pragma unroll
    for (int mi = 0; mi < 2; mi++)
#pragma unroll
        for (int ni = 0; ni < 8; ni++)
#pragma unroll
            for (int q = 0; q < 4; q++) c[mi][ni][q] = 0.0f;

    // prefetch chunk ch of GEMM1 into buffer ch&1
    auto pf1 = [&](int ch) {
        uint32_t b_u = sm_u + (ch & 1) * STGH * 2;
        const uint4* wsrc = (const uint4*)(g_w1h + (layer * 5 + ch) * 8192);
#pragma unroll
        for (int i = tid; i < 1024; i += 256) {
            int n = i >> 3, kq = i & 7;
            cpa16(b_u + 2 * (n * KW2 + kq * 8), wsrc + i);
        }
        uint32_t adst = b_u + 2 * (128 * KW2 + pr * KW2);
        if (ch < 4) {
            int node = (ch < 2) ? s_src[pr] : s_dst[pr];
            const __half* srcp = g_xh + node * HID + (ch & 1) * 64 + pq * 32;
#pragma unroll
            for (int q = 0; q < 4; q++)
                cpa16(adst + 2 * (pq * 32 + q * 8), srcp + q * 8);
        } else {
            cpa16(adst + 2 * (pq * 8), g_eah + (e0 + pr) * 16 + pq * 8);
        }
    };
    auto pf2 = [&](int ch) {
        uint32_t b_u = sm_u + ((ch + 1) & 1) * STGH * 2;
        const uint4* wsrc = (const uint4*)(g_w2h + (layer * 2 + ch) * 8192);
#pragma unroll
        for (int i = tid; i < 1024; i += 256) {
            int n = i >> 3, kq = i & 7;
            cpa16(b_u + 2 * (n * KW2 + kq * 8), wsrc + i);
        }
    };

    // ================= GEMM 1: chunks 0..3 (K=64 each) + tail chunk 4 (K=16)
    pf1(0); CPA_COMMIT();
    for (int ch = 0; ch < 5; ch++) {
        if (ch < 4) { pf1(ch + 1); CPA_COMMIT(); CPA_WAIT(1); }
        else        { CPA_WAIT(0); }
        __syncthreads();
        uint32_t b_u = sm_u + (ch & 1) * STGH * 2;
        uint32_t WU = b_u, AU = b_u + 2 * 128 * KW2;
        const int nks = (ch == 4) ? 1 : 4;
        for (int ks = 0; ks < nks; ks++) {
            uint32_t a[2][4];
            uint32_t ab = AU + 2 * ((wm * 32 + a_row) * KW2 + ks * 16 + a_k8);
            ldsm4(a[0], ab);
            ldsm4(a[1], ab + 2 * 16 * KW2);
#pragma unroll
            for (int p = 0; p < 4; p++) {
                uint32_t bh[4];
                uint32_t wb = 2 * ((wn * 64 + p * 16 + b_row) * KW2 + ks * 16 + b_k8);
                ldsm4(bh, WU + wb);
                mma16(c[0][2 * p], a[0], bh[0], bh[1]);
                mma16(c[1][2 * p], a[1], bh[0], bh[1]);
                mma16(c[0][2 * p + 1], a[0], bh[2], bh[3]);
                mma16(c[1][2 * p + 1], a[1], bh[2], bh[3]);
            }
        }
        __syncthreads();
    }

    // prefetch W2 chunk 0 while epilogue 1 runs
    pf2(0); CPA_COMMIT();

    // ---- epilogue 1: bias + silu -> fp16 H in Hs[128][136]
#pragma unroll
    for (int ni = 0; ni < 8; ni++) {
        int nb = wn * 64 + ni * 8 + 2 * t;
        float bx = s_b1[nb], by = s_b1[nb + 1];
#pragma unroll
        for (int mi = 0; mi < 2; mi++) {
            int r0 = wm * 32 + mi * 16 + g;
            uint32_t p0 = ph2(silu_f(c[mi][ni][0] + bx), silu_f(c[mi][ni][1] + by));
            uint32_t p1 = ph2(silu_f(c[mi][ni][2] + bx), silu_f(c[mi][ni][3] + by));
            *(uint32_t*)(Hs + r0 * HSB + nb) = p0;
            *(uint32_t*)(Hs + (r0 + 8) * HSB + nb) = p1;
            c[mi][ni][0] = c[mi][ni][1] = c[mi][ni][2] = c[mi][ni][3] = 0.0f;
        }
    }

    // ================= GEMM 2: K=128, 2 chunks of 64, A = Hs (fp16)
    for (int ch = 0; ch < 2; ch++) {
        if (ch < 1) { pf2(1); CPA_COMMIT(); CPA_WAIT(1); }
        else        { CPA_WAIT(0); }
        __syncthreads();
        uint32_t WU = sm_u + ((ch + 1) & 1) * STGH * 2;
#pragma unroll
        for (int ks = 0; ks < 4; ks++) {
            uint32_t a[2][4];
            uint32_t ab = Hs_u + 2 * ((wm * 32 + a_row) * HSB + ch * 64 + ks * 16 + a_k8);
            ldsm4(a[0], ab);
            ldsm4(a[1], ab + 2 * 16 * HSB);
#pragma unroll
            for (int p = 0; p < 4; p++) {
                uint32_t bh[4];
                uint32_t wb = 2 * ((wn * 64 + p * 16 + b_row) * KW2 + ks * 16 + b_k8);
                ldsm4(bh, WU + wb);
                mma16(c[0][2 * p], a[0], bh[0], bh[1]);
                mma16(c[1][2 * p], a[1], bh[0], bh[1]);
                mma16(c[0][2 * p + 1], a[0], bh[2], bh[3]);
                mma16(c[1][2 * p + 1], a[1], bh[2], bh[3]);
            }
        }
        __syncthreads();
    }

    // ---- epilogue 2: bias + silu, stage fp32 per 64-col half, coalesced scatter
    float* Ms = (float*)Hs;  // [128][68] fp32
#pragma unroll
    for (int h = 0; h < 2; h++) {
        __syncthreads();
        if (wn == h) {
#pragma unroll
            for (int ni = 0; ni < 8; ni++) {
                int nb = ni * 8 + 2 * t;
                float bx = s_b2[h * 64 + nb], by = s_b2[h * 64 + nb + 1];
#pragma unroll
                for (int mi = 0; mi < 2; mi++) {
                    int r0 = wm * 32 + mi * 16 + g;
                    float2 m0, m1;
                    m0.x = silu_f(c[mi][ni][0] + bx);
                    m0.y = silu_f(c[mi][ni][1] + by);
                    m1.x = silu_f(c[mi][ni][2] + bx);
                    m1.y = silu_f(c[mi][ni][3] + by);
                    *(float2*)(Ms + r0 * 68 + nb) = m0;
                    *(float2*)(Ms + (r0 + 8) * 68 + nb) = m1;
                }
            }
        }
        __syncthreads();
#pragma unroll
        for (int i = 0; i < 8; i++) {
            int idx2 = tid + i * 256;
            int row = idx2 >> 4, c4 = idx2 & 15;
            float4 v = *(const float4*)(Ms + row * 68 + c4 * 4);
            atomicAdd((float4*)(g_agg + s_dst[row] * HID + h * 64 + c4 * 4), v);
        }
    }
}

// ---------------------------------------------------------------------------
// Node update: fp16 tensor cores + cp.async. Block = 128 nodes, 256 threads.
// K = 256 (x || agg) in 4 chunks of 64. x via cp.async from g_xh; agg manual.
// ---------------------------------------------------------------------------
__global__ __launch_bounds__(256, 2)
void node_tc_kernel(const float* __restrict__ nbv, int layer) {
    extern __shared__ __half sm[];
    __half* Hs = sm + 2 * STGH;
    __shared__ float s_nb[HID];

    const int tid = threadIdx.x;
    const int lane = tid & 31, wid = tid >> 5;
    const int g = lane >> 2, t = lane & 3;
    const int wm = wid & 3, wn = wid >> 2;
    const int n0 = blockIdx.x * 128;

    const int lm = lane & 7, lt = lane >> 3;
    const int a_row = (lt & 1) * 8 + lm, a_k8 = (lt >> 1) * 8;
    const int b_row = (lt >> 1) * 8 + lm, b_k8 = (lt & 1) * 8;

    const uint32_t sm_u = (uint32_t)__cvta_generic_to_shared(sm);
    const int pr = tid >> 1, pq = tid & 1;

    if (tid < 128) s_nb[tid] = nbv[layer * HID + tid];
    __syncthreads();

    float c[2][8][4];
#pragma unroll
    for (int mi = 0; mi < 2; mi++)
#pragma unroll
        for (int ni = 0; ni < 8; ni++)
#pragma unroll
            for (int q = 0; q < 4; q++) c[mi][ni][q] = 0.0f;

    auto pfN = [&](int ch) {
        uint32_t b_u = sm_u + (ch & 1) * STGH * 2;
        const uint4* wsrc = (const uint4*)(g_nwh + (layer * 4 + ch) * 8192);
#pragma unroll
        for (int i = tid; i < 1024; i += 256) {
            int n = i >> 3, kq = i & 7;
            cpa16(b_u + 2 * (n * KW2 + kq * 8), wsrc + i);
        }
        int node = n0 + pr;
        uint32_t adst = b_u + 2 * (128 * KW2 + pr * KW2);
        __half* adst_p = sm + (ch & 1) * STGH + 128 * KW2 + pr * KW2;
        if (ch < 2) {
            if (node < N_NODES) {
                const __half* srcp = g_xh + node * HID + ch * 64 + pq * 32;
#pragma unroll
                for (int q = 0; q < 4; q++)
                    cpa16(adst + 2 * (pq * 32 + q * 8), srcp + q * 8);
            } else {
                uint4 zz = make_uint4(0u, 0u, 0u, 0u);
#pragma unroll
                for (int q = 0; q < 4; q++)
                    *(uint4*)(adst_p + pq * 32 + q * 8) = zz;
            }
        } else {
            uint4 o0 = make_uint4(0u, 0u, 0u, 0u), o1 = o0;
            if (node < N_NODES) {
                const float4* Xg = (const float4*)(g_agg + node * HID + (ch - 2) * 64 + pq * 32);
                float4 v0 = Xg[0], v1 = Xg[1], v2 = Xg[2], v3 = Xg[3];
                o0.x = ph2(v0.x, v0.y); o0.y = ph2(v0.z, v0.w);
                o0.z = ph2(v1.x, v1.y); o0.w = ph2(v1.z, v1.w);
                o1.x = ph2(v2.x, v2.y); o1.y = ph2(v2.z, v2.w);
                o1.z = ph2(v3.x, v3.y); o1.w = ph2(v3.z, v3.w);
                float4 v4 = Xg[4], v5 = Xg[5], v6 = Xg[6], v7 = Xg[7];
                uint4 o2, o3;
                o2.x = ph2(v4.x, v4.y); o2.y = ph2(v4.z, v4.w);
                o2.z = ph2(v5.x, v5.y); o2.w = ph2(v5.z, v5.w);
                o3.x = ph2(v6.x, v6.y); o3.y = ph2(v6.z, v6.w);
                o3.z = ph2(v7.x, v7.y); o3.w = ph2(v7.z, v7.w);
                *(uint4*)(adst_p + pq * 32) = o0;
                *(uint4*)(adst_p + pq * 32 + 8) = o1;
                *(uint4*)(adst_p + pq * 32 + 16) = o2;
                *(uint4*)(adst_p + pq * 32 + 24) = o3;
            } else {
                uint4 zz = make_uint4(0u, 0u, 0u, 0u);
#pragma unroll
                for (int q = 0; q < 4; q++)
                    *(uint4*)(adst_p + pq * 32 + q * 8) = zz;
            }
        }
    };

    pfN(0); CPA_COMMIT();
    for (int ch = 0; ch < 4; ch++) {
        if (ch < 3) { pfN(ch + 1); CPA_COMMIT(); CPA_WAIT(1); }
        else        { CPA_WAIT(0); }
        __syncthreads();
        uint32_t b_u = sm_u + (ch & 1) * STGH * 2;
        uint32_t WU = b_u, AU = b_u + 2 * 128 * KW2;
#pragma unroll
        for (int ks = 0; ks < 4; ks++) {
            uint32_t a[2][4];
            uint32_t ab = AU + 2 * ((wm * 32 + a_row) * KW2 + ks * 16 + a_k8);
            ldsm4(a[0], ab);
            ldsm4(a[1], ab + 2 * 16 * KW2);
#pragma unroll
            for (int p = 0; p < 4; p++) {
                uint32_t bh[4];
                uint32_t wb = 2 * ((wn * 64 + p * 16 + b_row) * KW2 + ks * 16 + b_k8);
                ldsm4(bh, WU + wb);
                mma16(c[0][2 * p], a[0], bh[0], bh[1]);
                mma16(c[1][2 * p], a[1], bh[0], bh[1]);
                mma16(c[0][2 * p + 1], a[0], bh[2], bh[3]);
                mma16(c[1][2 * p + 1], a[1], bh[2], bh[3]);
            }
        }
        __syncthreads();
    }

    // epilogue: bias + silu, stage per half, store g_x + g_xh, zero agg
    float* Ms = (float*)Hs;  // [128][68]
#pragma unroll
    for (int h = 0; h < 2; h++) {
        __syncthreads();
        if (wn == h) {
#pragma unroll
            for (int ni = 0; ni < 8; ni++) {
                int nb = ni * 8 + 2 * t;
                float bx = s_nb[h * 64 + nb], by = s_nb[h * 64 + nb + 1];
#pragma unroll
                for (int mi = 0; mi < 2; mi++) {
                    int r0 = wm * 32 + mi * 16 + g;
                    float2 m0, m1;
                    m0.x = silu_f(c[mi][ni][0] + bx);
                    m0.y = silu_f(c[mi][ni][1] + by);
                    m1.x = silu_f(c[mi][ni][2] + bx);
                    m1.y = silu_f(c[mi][ni][3] + by);
                    *(float2*)(Ms + r0 * 68 + nb) = m0;
                    *(float2*)(Ms + (r0 + 8) * 68 + nb) = m1;
                }
            }
        }
        __syncthreads();
        float4 z4 = make_float4(0.f, 0.f, 0.f, 0.f);
#pragma unroll
        for (int i = 0; i < 8; i++) {
            int idx2 = tid + i * 256;
            int row = idx2 >> 4, c4 = idx2 & 15;
            int node = n0 + row;
            if (node < N_NODES) {
                float4 v = *(const float4*)(Ms + row * 68 + c4 * 4);
                *(float4*)(g_x + node * HID + h * 64 + c4 * 4) = v;
                uint2 bv;
                bv.x = ph2(v.x, v.y);
                bv.y = ph2(v.z, v.w);
                *(uint2*)(g_xh + node * HID + h * 64 + c4 * 4) = bv;
                *(float4*)(g_agg + node * HID + h * 64 + c4 * 4) = z4;
            }
        }
    }
}

// ---------------------------------------------------------------------------
__global__ void pool_kernel(const int* __restrict__ batch) {
    int idx = blockIdx.x * 256 + threadIdx.x;
    if (idx < N_NODES * 32) {
        int n = idx >> 5, c = idx & 31;
        int b = batch[n];
        float4 v = ((const float4*)g_x)[idx];
        atomicAdd((float4*)(g_gsum + b * HID + c * 4), v);
        if (c == 0) atomicAdd(&g_gcnt[b], 1.0f);
    }
}

__global__ void readout_kernel(const float* __restrict__ rw1, const float* __restrict__ rb1,
                               const float* __restrict__ rw2, const float* __restrict__ rb2,
                               float* __restrict__ out) {
    __shared__ float gsh[HID];
    __shared__ float part[4];
    int g = blockIdx.x, j = threadIdx.x;
    float cnt = fmaxf(g_gcnt[g], 1.0f);
    gsh[j] = g_gsum[g * HID + j] / cnt;
    __syncthreads();
    float s = rb1[j];
#pragma unroll
    for (int k = 0; k < HID; k++) s += gsh[k] * rw1[k * HID + j];
    float v = silu_f(s) * rw2[j];
#pragma unroll
    for (int off = 16; off > 0; off >>= 1) v += __shfl_xor_sync(0xffffffffu, v, off);
    if ((j & 31) == 0) part[j >> 5] = v;
    __syncthreads();
    if (j == 0) out[g] = part[0] + part[1] + part[2] + part[3] + rb2[0];
}

// ---------------------------------------------------------------------------
extern "C" void kernel_launch(void* const* d_in, const int* in_sizes, int n_in,
                              void* d_out, int out_size) {
    const int*   z    = (const int*)d_in[0];
    const int*   ei   = (const int*)d_in[1];
    const float* ea   = (const float*)d_in[2];
    const int*   batch= (const int*)d_in[3];
    const float* emb  = (const float*)d_in[4];
    const float* ew1  = (const float*)d_in[5];
    const float* eb1  = (const float*)d_in[6];
    const float* ew2  = (const float*)d_in[7];
    const float* eb2  = (const float*)d_in[8];
    const float* nw   = (const float*)d_in[9];
    const float* nb   = (const float*)d_in[10];
    const float* rw1  = (const float*)d_in[11];
    const float* rb1  = (const float*)d_in[12];
    const float* rw2  = (const float*)d_in[13];
    const float* rb2  = (const float*)d_in[14];
    float* out = (float*)d_out;

    cudaFuncSetAttribute(edge_tc_kernel, cudaFuncAttributeMaxDynamicSharedMemorySize, EDGE_SMEM);
    cudaFuncSetAttribute(node_tc_kernel, cudaFuncAttributeMaxDynamicSharedMemorySize, EDGE_SMEM);

    pack_w_kernel<<<(LAYERS * 5 * 128 * 64 + 255) / 256, 256>>>(ew1, ew2, nw);
    ea_pack_kernel<<<(N_EDGES + 255) / 256, 256>>>(ea);
    embed_kernel<<<(N_NODES * HID + 255) / 256, 256>>>(z, emb);
    for (int l = 0; l < LAYERS; l++) {
        edge_tc_kernel<<<N_EDGES / 128, 256, EDGE_SMEM>>>(ei, eb1, eb2, l);
        node_tc_kernel<<<(N_NODES + 127) / 128, 256, EDGE_SMEM>>>(nb, l);
    }
    pool_kernel<<<(N_NODES * 32 + 255) / 256, 256>>>(batch);
    readout_kernel<<<NUM_GRAPHS, HID>>>(rw1, rb1, rw2, rb2, out);
}